// round 1
// baseline (speedup 1.0000x reference)
#include <cuda_runtime.h>
#include <math.h>

// Problem constants (shapes are fixed by the dataset)
#define NN   50000
#define EE   800000
#define FIN  512
#define FHID 256
#define FMID 128
#define FOUT 64

// ---------------- scratch (static device globals; no allocation) -------------
__device__ float g_h1  [(size_t)NN * FHID];   // x @ W1, later reused as relu output x2
__device__ float g_agg1[(size_t)NN * FHID];
__device__ float g_h2  [(size_t)NN * FMID];   // x2 @ W2, later reused as relu output x3
__device__ float g_agg2[(size_t)NN * FMID];
__device__ float g_deg [NN];                  // degree accumulator -> dinv (in place)

// ---------------- degree / dinv ---------------------------------------------
__global__ void k_deg_init(int n) {
    int i = blockIdx.x * blockDim.x + threadIdx.x;
    if (i < n) g_deg[i] = 1.0f;
}
__global__ void k_deg_count(const int* __restrict__ dst, int e) {
    int i = blockIdx.x * blockDim.x + threadIdx.x;
    if (i < e) atomicAdd(&g_deg[dst[i]], 1.0f);
}
__global__ void k_deg_fin(int n) {
    int i = blockIdx.x * blockDim.x + threadIdx.x;
    if (i < n) g_deg[i] = rsqrtf(g_deg[i]);
}

// ---------------- SGEMM: C[M,N] = A[M,K] @ B[K,N], all row-major -------------
// BM=128, BN=128, BK=8, TM=8, TN=8, 256 threads
__global__ __launch_bounds__(256) void sgemm128(
    int M, int N, int K,
    const float* __restrict__ A, const float* __restrict__ B, float* __restrict__ C)
{
    const int BM = 128, BN = 128, BK = 8, TM = 8, TN = 8;
    __shared__ float As[BK][BM];
    __shared__ float Bs[BK][BN];

    int bx = blockIdx.x;          // N tile
    int by = blockIdx.y;          // M tile
    int tid = threadIdx.x;

    int tcol = tid % (BN / TN);   // 0..15
    int trow = tid / (BN / TN);   // 0..15

    // A loads: each thread one float4 along K; BM*BK/4 = 256 float4s
    int aRow  = tid >> 1;               // 0..127
    int aCol4 = (tid & 1) * 4;          // 0 or 4
    // B loads: each thread one float4 along N
    int bRow  = tid >> 5;               // 0..7
    int bCol4 = (tid & 31) * 4;         // 0..124

    float acc[TM][TN];
    #pragma unroll
    for (int i = 0; i < TM; i++)
        #pragma unroll
        for (int j = 0; j < TN; j++) acc[i][j] = 0.0f;

    const float* Ab = A + (size_t)by * BM * K;
    const float* Bb = B + (size_t)bx * BN;
    int gArow = by * BM + aRow;

    for (int k0 = 0; k0 < K; k0 += BK) {
        float4 av = make_float4(0.f, 0.f, 0.f, 0.f);
        if (gArow < M)
            av = *(const float4*)(Ab + (size_t)aRow * K + k0 + aCol4);
        As[aCol4 + 0][aRow] = av.x;
        As[aCol4 + 1][aRow] = av.y;
        As[aCol4 + 2][aRow] = av.z;
        As[aCol4 + 3][aRow] = av.w;

        float4 bv = *(const float4*)(Bb + (size_t)(k0 + bRow) * N + bCol4);
        *(float4*)&Bs[bRow][bCol4] = bv;
        __syncthreads();

        #pragma unroll
        for (int kk = 0; kk < BK; kk++) {
            float ar[TM], br[TN];
            #pragma unroll
            for (int i = 0; i < TM; i++) ar[i] = As[kk][trow * TM + i];
            #pragma unroll
            for (int j = 0; j < TN; j++) br[j] = Bs[kk][tcol * TN + j];
            #pragma unroll
            for (int i = 0; i < TM; i++)
                #pragma unroll
                for (int j = 0; j < TN; j++)
                    acc[i][j] = fmaf(ar[i], br[j], acc[i][j]);
        }
        __syncthreads();
    }

    #pragma unroll
    for (int i = 0; i < TM; i++) {
        int gr = by * BM + trow * TM + i;
        if (gr < M) {
            #pragma unroll
            for (int j = 0; j < TN; j += 4) {
                float4 v = make_float4(acc[i][j], acc[i][j+1], acc[i][j+2], acc[i][j+3]);
                *(float4*)(C + (size_t)gr * N + bx * BN + tcol * TN + j) = v;
            }
        }
    }
}

// ---------------- agg init with self-loop term: agg = h * dinv^2 -------------
__global__ void k_selfinit(const float* __restrict__ h, float* __restrict__ agg,
                           int n, int F)
{
    size_t idx = (size_t)blockIdx.x * blockDim.x + threadIdx.x;   // over n*F/4
    size_t tot = (size_t)n * F / 4;
    if (idx >= tot) return;
    int row = (int)(idx / (F / 4));
    float d = g_deg[row];          // dinv
    d = d * d;
    float4 v = ((const float4*)h)[idx];
    v.x *= d; v.y *= d; v.z *= d; v.w *= d;
    ((float4*)agg)[idx] = v;
}

// ---------------- edge scatter: one warp per edge ----------------------------
__global__ __launch_bounds__(256) void k_scatter(
    const int* __restrict__ src, const int* __restrict__ dst,
    const float* __restrict__ h, float* __restrict__ agg, int E, int F)
{
    int warp = (int)(((size_t)blockIdx.x * blockDim.x + threadIdx.x) >> 5);
    int lane = threadIdx.x & 31;
    if (warp >= E) return;
    int s = src[warp], d = dst[warp];
    float norm = g_deg[s] * g_deg[d];
    const float4* hs = (const float4*)(h + (size_t)s * F);
    float* ad = agg + (size_t)d * F;
    int F4 = F >> 2;
    for (int f4 = lane; f4 < F4; f4 += 32) {
        float4 v = hs[f4];
        v.x *= norm; v.y *= norm; v.z *= norm; v.w *= norm;
        asm volatile("red.global.add.v4.f32 [%0], {%1,%2,%3,%4};"
                     :: "l"(ad + (size_t)f4 * 4), "f"(v.x), "f"(v.y), "f"(v.z), "f"(v.w)
                     : "memory");
    }
}

// ---------------- relu(agg + bias) -------------------------------------------
__global__ void k_relu_bias(const float* __restrict__ agg, const float* __restrict__ b,
                            float* __restrict__ out, int n, int F)
{
    size_t idx = (size_t)blockIdx.x * blockDim.x + threadIdx.x;   // over n*F/4
    size_t tot = (size_t)n * F / 4;
    if (idx >= tot) return;
    int col4 = (int)(idx % (F / 4));
    float4 bv = ((const float4*)b)[col4];
    float4 v  = ((const float4*)agg)[idx];
    v.x = fmaxf(v.x + bv.x, 0.f);
    v.y = fmaxf(v.y + bv.y, 0.f);
    v.z = fmaxf(v.z + bv.z, 0.f);
    v.w = fmaxf(v.w + bv.w, 0.f);
    ((float4*)out)[idx] = v;
}

// ---------------- classifier + log_softmax -----------------------------------
// blockDim (64, 4): 4 rows per block, 64 output classes per row.
__global__ __launch_bounds__(256) void k_cls(
    const float* __restrict__ X, const float* __restrict__ Wc,
    const float* __restrict__ bc, float* __restrict__ out, int n)
{
    __shared__ float sW[FMID * FOUT];     // 32 KB
    __shared__ float sx[4][FMID];
    __shared__ float smax[4][2];
    __shared__ float ssum[4][2];

    int t  = threadIdx.x;                 // 0..63 (output class)
    int ry = threadIdx.y;                 // 0..3  (row in block)
    int tid = ry * 64 + t;
    int row = blockIdx.x * 4 + ry;

    for (int i = tid; i < FMID * FOUT; i += 256) sW[i] = Wc[i];
    if (row < n)
        for (int k = t; k < FMID; k += 64) sx[ry][k] = X[(size_t)row * FMID + k];
    __syncthreads();

    float acc = bc[t];
    if (row < n) {
        #pragma unroll 8
        for (int k = 0; k < FMID; k++)
            acc = fmaf(sx[ry][k], sW[k * FOUT + t], acc);
    }

    // max over 64 threads (2 warps)
    float m = acc;
    #pragma unroll
    for (int o = 16; o; o >>= 1) m = fmaxf(m, __shfl_xor_sync(0xffffffffu, m, o));
    if ((t & 31) == 0) smax[ry][t >> 5] = m;
    __syncthreads();
    float rowmax = fmaxf(smax[ry][0], smax[ry][1]);

    float e = expf(acc - rowmax);
    float s = e;
    #pragma unroll
    for (int o = 16; o; o >>= 1) s += __shfl_xor_sync(0xffffffffu, s, o);
    if ((t & 31) == 0) ssum[ry][t >> 5] = s;
    __syncthreads();
    float rowsum = ssum[ry][0] + ssum[ry][1];

    if (row < n)
        out[(size_t)row * FOUT + t] = acc - rowmax - logf(rowsum);
}

// ---------------- launch ------------------------------------------------------
extern "C" void kernel_launch(void* const* d_in, const int* in_sizes, int n_in,
                              void* d_out, int out_size)
{
    const float* x   = (const float*)d_in[0];
    const int*   ei  = (const int*)  d_in[1];
    const float* W1  = (const float*)d_in[2];
    const float* b1  = (const float*)d_in[3];
    const float* W2  = (const float*)d_in[4];
    const float* b2  = (const float*)d_in[5];
    const float* Wc  = (const float*)d_in[6];
    const float* bc  = (const float*)d_in[7];
    float* out = (float*)d_out;

    int N = in_sizes[0] / FIN;
    int E = in_sizes[1] / 2;
    const int* src = ei;
    const int* dst = ei + E;

    float *h1, *agg1, *h2, *agg2;
    cudaGetSymbolAddress((void**)&h1,   g_h1);
    cudaGetSymbolAddress((void**)&agg1, g_agg1);
    cudaGetSymbolAddress((void**)&h2,   g_h2);
    cudaGetSymbolAddress((void**)&agg2, g_agg2);

    // degrees -> dinv
    k_deg_init <<<(N + 255) / 256, 256>>>(N);
    k_deg_count<<<(E + 255) / 256, 256>>>(dst, E);
    k_deg_fin  <<<(N + 255) / 256, 256>>>(N);

    // layer 1: h1 = x @ W1
    {
        dim3 grid(FHID / 128, (N + 127) / 128);
        sgemm128<<<grid, 256>>>(N, FHID, FIN, x, W1, h1);
    }
    {
        size_t tot = (size_t)N * FHID / 4;
        k_selfinit<<<(unsigned)((tot + 255) / 256), 256>>>(h1, agg1, N, FHID);
    }
    k_scatter<<<(E * 32 + 255) / 256, 256>>>(src, dst, h1, agg1, E, FHID);
    {
        size_t tot = (size_t)N * FHID / 4;
        k_relu_bias<<<(unsigned)((tot + 255) / 256), 256>>>(agg1, b1, h1, N, FHID);  // h1 := x2
    }

    // layer 2: h2 = x2 @ W2
    {
        dim3 grid(FMID / 128, (N + 127) / 128);
        sgemm128<<<grid, 256>>>(N, FMID, FHID, h1, W2, h2);
    }
    {
        size_t tot = (size_t)N * FMID / 4;
        k_selfinit<<<(unsigned)((tot + 255) / 256), 256>>>(h2, agg2, N, FMID);
    }
    k_scatter<<<(E * 32 + 255) / 256, 256>>>(src, dst, h2, agg2, E, FMID);
    {
        size_t tot = (size_t)N * FMID / 4;
        k_relu_bias<<<(unsigned)((tot + 255) / 256), 256>>>(agg2, b2, h2, N, FMID);  // h2 := x3
    }

    // classifier + log_softmax
    {
        dim3 block(64, 4);
        k_cls<<<(N + 3) / 4, block>>>(h2, Wc, bc, out, N);
    }
}

// round 2
// speedup vs baseline: 1.3027x; 1.3027x over previous
#include <cuda_runtime.h>
#include <math.h>

#define NN   50000
#define EE   800000
#define FIN  512
#define FHID 256
#define FMID 128
#define FOUT 64

// ---------------- scratch (static device globals) ----------------------------
__device__ float g_h1  [(size_t)NN * FHID];   // h1' = (x@W1)*dinv[row]
__device__ float g_x2  [(size_t)NN * FHID];   // relu layer-1 output
__device__ float g_h2  [(size_t)NN * FMID];   // h2' = (x2@W2)*dinv[row]
__device__ float g_x3  [(size_t)NN * FMID];   // relu layer-2 output
__device__ float g_deg [NN];                  // dinv = rsqrt(1 + indeg)
__device__ int   g_cnt [NN];
__device__ int   g_off [NN + 1];
__device__ int   g_pos [NN];
__device__ int   g_csr [EE];

// ---------------- degree / CSR build -----------------------------------------
__global__ void k_zero(int n) {
    int i = blockIdx.x * blockDim.x + threadIdx.x;
    if (i < n) g_cnt[i] = 0;
}
__global__ void k_hist(const int* __restrict__ dst, int e) {
    int i = blockIdx.x * blockDim.x + threadIdx.x;
    if (i < e) atomicAdd(&g_cnt[dst[i]], 1);
}
__global__ void k_dinv(int n) {
    int i = blockIdx.x * blockDim.x + threadIdx.x;
    if (i < n) g_deg[i] = rsqrtf(1.0f + (float)g_cnt[i]);
}
// single-block exclusive scan of g_cnt -> g_off, g_pos
__global__ __launch_bounds__(1024) void k_scan(int n) {
    __shared__ int part[1024];
    int t = threadIdx.x;
    const int C = (NN + 1023) / 1024;
    int beg = t * C, end = min(beg + C, n);
    int s = 0;
    for (int i = beg; i < end; i++) s += g_cnt[i];
    part[t] = s;
    __syncthreads();
    for (int o = 1; o < 1024; o <<= 1) {
        int v = (t >= o) ? part[t - o] : 0;
        __syncthreads();
        part[t] += v;
        __syncthreads();
    }
    int excl = (t == 0) ? 0 : part[t - 1];
    for (int i = beg; i < end; i++) {
        g_off[i] = excl; g_pos[i] = excl;
        excl += g_cnt[i];
    }
    if (t == 1023) g_off[n] = excl;
}
__global__ void k_fill(const int* __restrict__ src, const int* __restrict__ dst, int e) {
    int i = blockIdx.x * blockDim.x + threadIdx.x;
    if (i < e) {
        int d = dst[i];
        int p = atomicAdd(&g_pos[d], 1);
        g_csr[p] = src[i];
    }
}

// ---------------- tf32 tensor-core GEMM --------------------------------------
// C[M,N] = (A[M,K] @ B[K,N]) * dinv[row]
// BM=128, BN=128, BK=16, 256 threads (8 warps, 2x4), warp tile 64x32
__device__ __forceinline__ unsigned f2tf(float x) {
    unsigned r;
    asm("cvt.rna.tf32.f32 %0, %1;" : "=r"(r) : "f"(x));
    return r;
}

__global__ __launch_bounds__(256) void sgemm_tf32(
    int M, int N, int K,
    const float* __restrict__ A, const float* __restrict__ B, float* __restrict__ C)
{
    const int BM = 128, BN = 128, BK = 16;
    __shared__ unsigned As[BM][BK + 4];   // [m][k], pad 4 -> conflict-free frag reads
    __shared__ unsigned Bs[BK][BN + 8];   // [k][n], pad 8 -> conflict-free frag reads

    int tid  = threadIdx.x;
    int lane = tid & 31;
    int warp = tid >> 5;
    int warpm = warp >> 2;            // 0..1
    int warpn = warp & 3;             // 0..3

    int blockM = blockIdx.y * BM;
    int blockN = blockIdx.x * BN;

    float c[4][4][4];
    #pragma unroll
    for (int i = 0; i < 4; i++)
        #pragma unroll
        for (int j = 0; j < 4; j++)
            #pragma unroll
            for (int q = 0; q < 4; q++) c[i][j][q] = 0.0f;

    for (int k0 = 0; k0 < K; k0 += BK) {
        // load A tile: 512 float4s (128 rows x 4)
        #pragma unroll
        for (int li = 0; li < 2; li++) {
            int v = tid + li * 256;
            int row = v >> 2;
            int c4  = (v & 3) << 2;
            float4 av = make_float4(0.f, 0.f, 0.f, 0.f);
            if (blockM + row < M)
                av = *(const float4*)(A + (size_t)(blockM + row) * K + k0 + c4);
            As[row][c4 + 0] = f2tf(av.x);
            As[row][c4 + 1] = f2tf(av.y);
            As[row][c4 + 2] = f2tf(av.z);
            As[row][c4 + 3] = f2tf(av.w);
        }
        // load B tile: 512 float4s (16 rows x 32)
        #pragma unroll
        for (int li = 0; li < 2; li++) {
            int v = tid + li * 256;
            int row = v >> 5;
            int c4  = (v & 31) << 2;
            float4 bv = *(const float4*)(B + (size_t)(k0 + row) * N + blockN + c4);
            Bs[row][c4 + 0] = f2tf(bv.x);
            Bs[row][c4 + 1] = f2tf(bv.y);
            Bs[row][c4 + 2] = f2tf(bv.z);
            Bs[row][c4 + 3] = f2tf(bv.w);
        }
        __syncthreads();

        #pragma unroll
        for (int ks = 0; ks < BK; ks += 8) {
            unsigned a[4][4], b[4][2];
            int ar = (lane >> 2);
            int ac = ks + (lane & 3);
            #pragma unroll
            for (int i = 0; i < 4; i++) {
                int mb = warpm * 64 + i * 16;
                a[i][0] = As[mb + ar    ][ac    ];
                a[i][1] = As[mb + ar + 8][ac    ];
                a[i][2] = As[mb + ar    ][ac + 4];
                a[i][3] = As[mb + ar + 8][ac + 4];
            }
            int br = ks + (lane & 3);
            int bc = (lane >> 2);
            #pragma unroll
            for (int j = 0; j < 4; j++) {
                int nb = warpn * 32 + j * 8;
                b[j][0] = Bs[br    ][nb + bc];
                b[j][1] = Bs[br + 4][nb + bc];
            }
            #pragma unroll
            for (int i = 0; i < 4; i++)
                #pragma unroll
                for (int j = 0; j < 4; j++) {
                    asm volatile(
                        "mma.sync.aligned.m16n8k8.row.col.f32.tf32.tf32.f32 "
                        "{%0,%1,%2,%3},{%4,%5,%6,%7},{%8,%9},{%0,%1,%2,%3};"
                        : "+f"(c[i][j][0]), "+f"(c[i][j][1]),
                          "+f"(c[i][j][2]), "+f"(c[i][j][3])
                        : "r"(a[i][0]), "r"(a[i][1]), "r"(a[i][2]), "r"(a[i][3]),
                          "r"(b[j][0]), "r"(b[j][1]));
                }
        }
        __syncthreads();
    }

    // epilogue: scale rows by dinv, write C
    #pragma unroll
    for (int i = 0; i < 4; i++) {
        int gr0 = blockM + warpm * 64 + i * 16 + (lane >> 2);
        int gr1 = gr0 + 8;
        float dv0 = (gr0 < M) ? g_deg[gr0] : 0.f;
        float dv1 = (gr1 < M) ? g_deg[gr1] : 0.f;
        #pragma unroll
        for (int j = 0; j < 4; j++) {
            int gc = blockN + warpn * 32 + j * 8 + 2 * (lane & 3);
            if (gr0 < M) {
                float2 v0 = make_float2(c[i][j][0] * dv0, c[i][j][1] * dv0);
                *(float2*)(C + (size_t)gr0 * N + gc) = v0;
            }
            if (gr1 < M) {
                float2 v1 = make_float2(c[i][j][2] * dv1, c[i][j][3] * dv1);
                *(float2*)(C + (size_t)gr1 * N + gc) = v1;
            }
        }
    }
}

// ---------------- fused CSR aggregation + self-loop + bias + relu ------------
// out[d] = relu( dinv[d] * (h'[d] + sum_{s in in(d)} h'[s]) + b )
template<int F>
__global__ __launch_bounds__(128) void k_agg(
    const float* __restrict__ hp, const float* __restrict__ b,
    float* __restrict__ out)
{
    const int PF = F / 128;
    __shared__ int sids[128];
    int node = blockIdx.x;
    int t = threadIdx.x;

    int beg = g_off[node], end = g_off[node + 1];
    float acc[PF];
    #pragma unroll
    for (int p = 0; p < PF; p++) acc[p] = 0.0f;

    for (int e0 = beg; e0 < end; e0 += 128) {
        int ne = min(128, end - e0);
        __syncthreads();
        if (t < ne) sids[t] = g_csr[e0 + t];
        __syncthreads();
        int j = 0;
        #pragma unroll 4
        for (; j < ne; j++) {
            const float* row = hp + (size_t)sids[j] * F;
            #pragma unroll
            for (int p = 0; p < PF; p++) acc[p] += __ldg(row + t + p * 128);
        }
    }

    float dv = g_deg[node];
    const float* self = hp + (size_t)node * F;
    #pragma unroll
    for (int p = 0; p < PF; p++) {
        float v = dv * (acc[p] + self[t + p * 128]) + b[t + p * 128];
        out[(size_t)node * F + t + p * 128] = fmaxf(v, 0.0f);
    }
}

// ---------------- classifier + log_softmax -----------------------------------
__global__ __launch_bounds__(256) void k_cls(
    const float* __restrict__ X, const float* __restrict__ Wc,
    const float* __restrict__ bc, float* __restrict__ out, int n)
{
    __shared__ float sW[FMID * FOUT];
    __shared__ float sx[4][FMID];
    __shared__ float smax[4][2];
    __shared__ float ssum[4][2];

    int t  = threadIdx.x;
    int ry = threadIdx.y;
    int tid = ry * 64 + t;
    int row = blockIdx.x * 4 + ry;

    for (int i = tid; i < FMID * FOUT; i += 256) sW[i] = Wc[i];
    if (row < n)
        for (int k = t; k < FMID; k += 64) sx[ry][k] = X[(size_t)row * FMID + k];
    __syncthreads();

    float acc = bc[t];
    if (row < n) {
        #pragma unroll 8
        for (int k = 0; k < FMID; k++)
            acc = fmaf(sx[ry][k], sW[k * FOUT + t], acc);
    }

    float m = acc;
    #pragma unroll
    for (int o = 16; o; o >>= 1) m = fmaxf(m, __shfl_xor_sync(0xffffffffu, m, o));
    if ((t & 31) == 0) smax[ry][t >> 5] = m;
    __syncthreads();
    float rowmax = fmaxf(smax[ry][0], smax[ry][1]);

    float e = expf(acc - rowmax);
    float s = e;
    #pragma unroll
    for (int o = 16; o; o >>= 1) s += __shfl_xor_sync(0xffffffffu, s, o);
    if ((t & 31) == 0) ssum[ry][t >> 5] = s;
    __syncthreads();
    float rowsum = ssum[ry][0] + ssum[ry][1];

    if (row < n)
        out[(size_t)row * FOUT + t] = acc - rowmax - logf(rowsum);
}

// ---------------- launch ------------------------------------------------------
extern "C" void kernel_launch(void* const* d_in, const int* in_sizes, int n_in,
                              void* d_out, int out_size)
{
    const float* x   = (const float*)d_in[0];
    const int*   ei  = (const int*)  d_in[1];
    const float* W1  = (const float*)d_in[2];
    const float* b1  = (const float*)d_in[3];
    const float* W2  = (const float*)d_in[4];
    const float* b2  = (const float*)d_in[5];
    const float* Wc  = (const float*)d_in[6];
    const float* bc  = (const float*)d_in[7];
    float* out = (float*)d_out;

    int N = in_sizes[0] / FIN;
    int E = in_sizes[1] / 2;
    const int* src = ei;
    const int* dst = ei + E;

    float *h1, *x2, *h2, *x3;
    cudaGetSymbolAddress((void**)&h1, g_h1);
    cudaGetSymbolAddress((void**)&x2, g_x2);
    cudaGetSymbolAddress((void**)&h2, g_h2);
    cudaGetSymbolAddress((void**)&x3, g_x3);

    // degrees + CSR
    k_zero<<<(N + 255) / 256, 256>>>(N);
    k_hist<<<(E + 255) / 256, 256>>>(dst, E);
    k_dinv<<<(N + 255) / 256, 256>>>(N);
    k_scan<<<1, 1024>>>(N);
    k_fill<<<(E + 255) / 256, 256>>>(src, dst, E);

    // layer 1
    {
        dim3 grid(FHID / 128, (N + 127) / 128);
        sgemm_tf32<<<grid, 256>>>(N, FHID, FIN, x, W1, h1);
    }
    k_agg<FHID><<<N, 128>>>(h1, b1, x2);

    // layer 2
    {
        dim3 grid(FMID / 128, (N + 127) / 128);
        sgemm_tf32<<<grid, 256>>>(N, FMID, FHID, x2, W2, h2);
    }
    k_agg<FMID><<<N, 128>>>(h2, b2, x3);

    // classifier + log_softmax
    {
        dim3 block(64, 4);
        k_cls<<<(N + 3) / 4, block>>>(x3, Wc, bc, out, N);
    }
}

// round 7
// speedup vs baseline: 2.3212x; 1.7819x over previous
#include <cuda_runtime.h>
#include <math.h>

#define NN   50000
#define EE   800000
#define FIN  512
#define FHID 256
#define FMID 128
#define FOUT 64

// ---------------- scratch (static device globals) ----------------------------
__device__ float g_h1  [(size_t)NN * FHID];
__device__ float g_x2  [(size_t)NN * FHID];
__device__ float g_h2  [(size_t)NN * FMID];
__device__ float g_x3  [(size_t)NN * FMID];
__device__ float g_deg [NN];
__device__ int   g_cnt [NN + 4];        // padded for int4 tail
__device__ int   g_off [NN + 1];
__device__ int   g_pos [NN];
__device__ int   g_csr [EE];
__device__ int   g_bsum[256];
__device__ int   g_bpre[256];

// ---------------- degree / CSR build -----------------------------------------
__global__ void k_zero(int n) {
    int i = blockIdx.x * blockDim.x + threadIdx.x;
    if (i < n + 4) g_cnt[i] = 0;
}
__global__ void k_hist(const int* __restrict__ dst, int e) {
    int i = blockIdx.x * blockDim.x + threadIdx.x;
    if (i < e) atomicAdd(&g_cnt[dst[i]], 1);
}
__global__ void k_dinv(int n) {
    int i = blockIdx.x * blockDim.x + threadIdx.x;
    if (i < n) g_deg[i] = rsqrtf(1.0f + (float)g_cnt[i]);
}

// Stage 1: per-block (1024 elements) sum of g_cnt -> g_bsum[b]
__global__ __launch_bounds__(256) void k_bsum(int n) {
    __shared__ int sw[8];
    int b = blockIdx.x, t = threadIdx.x;
    int base = b * 1024;
    int s = 0;
    #pragma unroll
    for (int j = 0; j < 4; j++) {
        int i = base + t + j * 256;
        if (i < n) s += g_cnt[i];
    }
    #pragma unroll
    for (int o = 16; o; o >>= 1) s += __shfl_xor_sync(0xffffffffu, s, o);
    if ((t & 31) == 0) sw[t >> 5] = s;
    __syncthreads();
    if (t == 0) {
        int tot = 0;
        #pragma unroll
        for (int w = 0; w < 8; w++) tot += sw[w];
        g_bsum[b] = tot;
    }
}

// Stage 2: tiny exclusive scan of block sums (nb <= 64), also writes g_off[n]
__global__ __launch_bounds__(64) void k_bscan(int nb, int n) {
    __shared__ int sv[64];
    int t = threadIdx.x;
    int v = (t < nb) ? g_bsum[t] : 0;
    sv[t] = v;
    __syncthreads();
    #pragma unroll
    for (int o = 1; o < 64; o <<= 1) {
        int u = (t >= o) ? sv[t - o] : 0;
        __syncthreads();
        sv[t] += u;
        __syncthreads();
    }
    if (t < nb) g_bpre[t] = sv[t] - v;          // exclusive
    if (t == nb - 1) g_off[n] = sv[t];          // total
}

// Stage 3: per-block exclusive scan over its 1024 counts -> g_off, g_pos
__global__ __launch_bounds__(256) void k_boff(int n) {
    __shared__ int sts[256];
    int b = blockIdx.x, t = threadIdx.x;
    int base = b * 1024 + t * 4;

    int c0 = 0, c1 = 0, c2 = 0, c3 = 0;
    if (base + 3 < n) {
        int4 v = *(const int4*)&g_cnt[base];
        c0 = v.x; c1 = v.y; c2 = v.z; c3 = v.w;
    } else {
        if (base + 0 < n) c0 = g_cnt[base + 0];
        if (base + 1 < n) c1 = g_cnt[base + 1];
        if (base + 2 < n) c2 = g_cnt[base + 2];
        if (base + 3 < n) c3 = g_cnt[base + 3];
    }
    int tsum = c0 + c1 + c2 + c3;
    sts[t] = tsum;
    __syncthreads();
    #pragma unroll
    for (int o = 1; o < 256; o <<= 1) {
        int u = (t >= o) ? sts[t - o] : 0;
        __syncthreads();
        sts[t] += u;
        __syncthreads();
    }
    int excl = g_bpre[b] + sts[t] - tsum;

    int o0 = excl;
    int o1 = o0 + c0;
    int o2 = o1 + c1;
    int o3 = o2 + c2;
    if (base + 3 < n) {
        *(int4*)&g_off[base] = make_int4(o0, o1, o2, o3);
        *(int4*)&g_pos[base] = make_int4(o0, o1, o2, o3);
    } else {
        if (base + 0 < n) { g_off[base + 0] = o0; g_pos[base + 0] = o0; }
        if (base + 1 < n) { g_off[base + 1] = o1; g_pos[base + 1] = o1; }
        if (base + 2 < n) { g_off[base + 2] = o2; g_pos[base + 2] = o2; }
        if (base + 3 < n) { g_off[base + 3] = o3; g_pos[base + 3] = o3; }
    }
}

__global__ void k_fill(const int* __restrict__ src, const int* __restrict__ dst, int e) {
    int i = blockIdx.x * blockDim.x + threadIdx.x;
    if (i < e) {
        int d = dst[i];
        int p = atomicAdd(&g_pos[d], 1);
        g_csr[p] = src[i];
    }
}

// ---------------- tf32 tensor-core GEMM --------------------------------------
__device__ __forceinline__ unsigned f2tf(float x) {
    unsigned r;
    asm("cvt.rna.tf32.f32 %0, %1;" : "=r"(r) : "f"(x));
    return r;
}

__global__ __launch_bounds__(256) void sgemm_tf32(
    int M, int N, int K,
    const float* __restrict__ A, const float* __restrict__ B, float* __restrict__ C)
{
    const int BM = 128, BN = 128, BK = 16;
    __shared__ unsigned As[BM][BK + 4];
    __shared__ unsigned Bs[BK][BN + 8];

    int tid  = threadIdx.x;
    int lane = tid & 31;
    int warp = tid >> 5;
    int warpm = warp >> 2;
    int warpn = warp & 3;

    int blockM = blockIdx.y * BM;
    int blockN = blockIdx.x * BN;

    float c[4][4][4];
    #pragma unroll
    for (int i = 0; i < 4; i++)
        #pragma unroll
        for (int j = 0; j < 4; j++)
            #pragma unroll
            for (int q = 0; q < 4; q++) c[i][j][q] = 0.0f;

    for (int k0 = 0; k0 < K; k0 += BK) {
        #pragma unroll
        for (int li = 0; li < 2; li++) {
            int v = tid + li * 256;
            int row = v >> 2;
            int c4  = (v & 3) << 2;
            float4 av = make_float4(0.f, 0.f, 0.f, 0.f);
            if (blockM + row < M)
                av = *(const float4*)(A + (size_t)(blockM + row) * K + k0 + c4);
            As[row][c4 + 0] = f2tf(av.x);
            As[row][c4 + 1] = f2tf(av.y);
            As[row][c4 + 2] = f2tf(av.z);
            As[row][c4 + 3] = f2tf(av.w);
        }
        #pragma unroll
        for (int li = 0; li < 2; li++) {
            int v = tid + li * 256;
            int row = v >> 5;
            int c4  = (v & 31) << 2;
            float4 bv = *(const float4*)(B + (size_t)(k0 + row) * N + blockN + c4);
            Bs[row][c4 + 0] = f2tf(bv.x);
            Bs[row][c4 + 1] = f2tf(bv.y);
            Bs[row][c4 + 2] = f2tf(bv.z);
            Bs[row][c4 + 3] = f2tf(bv.w);
        }
        __syncthreads();

        #pragma unroll
        for (int ks = 0; ks < BK; ks += 8) {
            unsigned a[4][4], b[4][2];
            int ar = (lane >> 2);
            int ac = ks + (lane & 3);
            #pragma unroll
            for (int i = 0; i < 4; i++) {
                int mb = warpm * 64 + i * 16;
                a[i][0] = As[mb + ar    ][ac    ];
                a[i][1] = As[mb + ar + 8][ac    ];
                a[i][2] = As[mb + ar    ][ac + 4];
                a[i][3] = As[mb + ar + 8][ac + 4];
            }
            int br = ks + (lane & 3);
            int bc = (lane >> 2);
            #pragma unroll
            for (int j = 0; j < 4; j++) {
                int nb = warpn * 32 + j * 8;
                b[j][0] = Bs[br    ][nb + bc];
                b[j][1] = Bs[br + 4][nb + bc];
            }
            #pragma unroll
            for (int i = 0; i < 4; i++)
                #pragma unroll
                for (int j = 0; j < 4; j++) {
                    asm volatile(
                        "mma.sync.aligned.m16n8k8.row.col.f32.tf32.tf32.f32 "
                        "{%0,%1,%2,%3},{%4,%5,%6,%7},{%8,%9},{%0,%1,%2,%3};"
                        : "+f"(c[i][j][0]), "+f"(c[i][j][1]),
                          "+f"(c[i][j][2]), "+f"(c[i][j][3])
                        : "r"(a[i][0]), "r"(a[i][1]), "r"(a[i][2]), "r"(a[i][3]),
                          "r"(b[j][0]), "r"(b[j][1]));
                }
        }
        __syncthreads();
    }

    #pragma unroll
    for (int i = 0; i < 4; i++) {
        int gr0 = blockM + warpm * 64 + i * 16 + (lane >> 2);
        int gr1 = gr0 + 8;
        float dv0 = (gr0 < M) ? g_deg[gr0] : 0.f;
        float dv1 = (gr1 < M) ? g_deg[gr1] : 0.f;
        #pragma unroll
        for (int j = 0; j < 4; j++) {
            int gc = blockN + warpn * 32 + j * 8 + 2 * (lane & 3);
            if (gr0 < M) {
                float2 v0 = make_float2(c[i][j][0] * dv0, c[i][j][1] * dv0);
                *(float2*)(C + (size_t)gr0 * N + gc) = v0;
            }
            if (gr1 < M) {
                float2 v1 = make_float2(c[i][j][2] * dv1, c[i][j][3] * dv1);
                *(float2*)(C + (size_t)gr1 * N + gc) = v1;
            }
        }
    }
}

// ---------------- fused CSR aggregation + self-loop + bias + relu ------------
template<int F>
__global__ __launch_bounds__(128) void k_agg(
    const float* __restrict__ hp, const float* __restrict__ b,
    float* __restrict__ out)
{
    const int PF = F / 128;
    __shared__ int sids[128];
    int node = blockIdx.x;
    int t = threadIdx.x;

    int beg = g_off[node], end = g_off[node + 1];
    float acc[PF];
    #pragma unroll
    for (int p = 0; p < PF; p++) acc[p] = 0.0f;

    for (int e0 = beg; e0 < end; e0 += 128) {
        int ne = min(128, end - e0);
        __syncthreads();
        if (t < ne) sids[t] = g_csr[e0 + t];
        __syncthreads();
        #pragma unroll 4
        for (int j = 0; j < ne; j++) {
            const float* row = hp + (size_t)sids[j] * F;
            #pragma unroll
            for (int p = 0; p < PF; p++) acc[p] += __ldg(row + t + p * 128);
        }
    }

    float dv = g_deg[node];
    const float* self = hp + (size_t)node * F;
    #pragma unroll
    for (int p = 0; p < PF; p++) {
        float v = dv * (acc[p] + self[t + p * 128]) + b[t + p * 128];
        out[(size_t)node * F + t + p * 128] = fmaxf(v, 0.0f);
    }
}

// ---------------- classifier + log_softmax -----------------------------------
// 512 threads = 8 rows x 64 classes; 2 row-iterations -> 16 rows per block.
__global__ __launch_bounds__(512) void k_cls(
    const float* __restrict__ X, const float* __restrict__ Wc,
    const float* __restrict__ bc, float* __restrict__ out, int n)
{
    __shared__ float sW[FMID * FOUT];     // 32 KB
    __shared__ float sx[8][FMID];
    __shared__ float smax[8][2];
    __shared__ float ssum[8][2];

    int t  = threadIdx.x;                 // 0..63
    int ry = threadIdx.y;                 // 0..7
    int tid = ry * 64 + t;

    for (int i = tid; i < FMID * FOUT; i += 512) sW[i] = Wc[i];
    float bias = bc[t];

    #pragma unroll
    for (int it = 0; it < 2; it++) {
        int row = blockIdx.x * 16 + it * 8 + ry;
        __syncthreads();
        if (row < n) {
            #pragma unroll
            for (int k = t; k < FMID; k += 64) sx[ry][k] = X[(size_t)row * FMID + k];
        }
        __syncthreads();

        float acc = bias;
        if (row < n) {
            #pragma unroll 8
            for (int k = 0; k < FMID; k++)
                acc = fmaf(sx[ry][k], sW[k * FOUT + t], acc);
        }

        float m = acc;
        #pragma unroll
        for (int o = 16; o; o >>= 1) m = fmaxf(m, __shfl_xor_sync(0xffffffffu, m, o));
        if ((t & 31) == 0) smax[ry][t >> 5] = m;
        __syncthreads();
        float rowmax = fmaxf(smax[ry][0], smax[ry][1]);

        float e = expf(acc - rowmax);
        float s = e;
        #pragma unroll
        for (int o = 16; o; o >>= 1) s += __shfl_xor_sync(0xffffffffu, s, o);
        if ((t & 31) == 0) ssum[ry][t >> 5] = s;
        __syncthreads();
        float rowsum = ssum[ry][0] + ssum[ry][1];

        if (row < n)
            out[(size_t)row * FOUT + t] = acc - rowmax - logf(rowsum);
    }
}

// ---------------- launch ------------------------------------------------------
extern "C" void kernel_launch(void* const* d_in, const int* in_sizes, int n_in,
                              void* d_out, int out_size)
{
    const float* x   = (const float*)d_in[0];
    const int*   ei  = (const int*)  d_in[1];
    const float* W1  = (const float*)d_in[2];
    const float* b1  = (const float*)d_in[3];
    const float* W2  = (const float*)d_in[4];
    const float* b2  = (const float*)d_in[5];
    const float* Wc  = (const float*)d_in[6];
    const float* bc  = (const float*)d_in[7];
    float* out = (float*)d_out;

    int N = in_sizes[0] / FIN;
    int E = in_sizes[1] / 2;
    const int* src = ei;
    const int* dst = ei + E;

    float *h1, *x2, *h2, *x3;
    cudaGetSymbolAddress((void**)&h1, g_h1);
    cudaGetSymbolAddress((void**)&x2, g_x2);
    cudaGetSymbolAddress((void**)&h2, g_h2);
    cudaGetSymbolAddress((void**)&x3, g_x3);

    int nb = (N + 1023) / 1024;           // blocks of 1024 counts

    // degrees + CSR
    k_zero<<<(N + 4 + 255) / 256, 256>>>(N);
    k_hist<<<(E + 255) / 256, 256>>>(dst, E);
    k_dinv<<<(N + 255) / 256, 256>>>(N);
    k_bsum<<<nb, 256>>>(N);
    k_bscan<<<1, 64>>>(nb, N);
    k_boff<<<nb, 256>>>(N);
    k_fill<<<(E + 255) / 256, 256>>>(src, dst, E);

    // layer 1
    {
        dim3 grid(FHID / 128, (N + 127) / 128);
        sgemm_tf32<<<grid, 256>>>(N, FHID, FIN, x, W1, h1);
    }
    k_agg<FHID><<<N, 128>>>(h1, b1, x2);

    // layer 2
    {
        dim3 grid(FMID / 128, (N + 127) / 128);
        sgemm_tf32<<<grid, 256>>>(N, FMID, FHID, x2, W2, h2);
    }
    k_agg<FMID><<<N, 128>>>(h2, b2, x3);

    // classifier + log_softmax
    {
        dim3 block(64, 8);
        k_cls<<<(N + 15) / 16, block>>>(x3, Wc, bc, out, N);
    }
}

// round 8
// speedup vs baseline: 2.5893x; 1.1155x over previous
#include <cuda_runtime.h>
#include <cuda_fp16.h>
#include <math.h>

#define NN   50000
#define EE   800000
#define FIN  512
#define FHID 256
#define FMID 128
#define FOUT 64

// ---------------- scratch (static device globals) ----------------------------
__device__ __half g_h1h[(size_t)NN * FHID];   // h1' = (x@W1)*dinv  (fp16)
__device__ float  g_x2 [(size_t)NN * FHID];   // relu layer-1 output (fp32)
__device__ __half g_h2h[(size_t)NN * FMID];   // h2' = (x2@W2)*dinv (fp16)
__device__ float  g_x3 [(size_t)NN * FMID];   // relu layer-2 output (fp32)
__device__ float  g_deg[NN];
__device__ int    g_cnt[NN + 4];
__device__ int    g_off[NN + 1];
__device__ int    g_pos[NN];
__device__ int    g_csr[EE];
__device__ int    g_bsum[256];
__device__ int    g_bpre[256];

// ---------------- degree / CSR build -----------------------------------------
__global__ void k_zero(int n) {
    int i = blockIdx.x * blockDim.x + threadIdx.x;
    if (i < n + 4) g_cnt[i] = 0;
}
__global__ void k_hist(const int* __restrict__ dst, int e) {
    int i = blockIdx.x * blockDim.x + threadIdx.x;
    if (i < e) atomicAdd(&g_cnt[dst[i]], 1);
}
__global__ void k_dinv(int n) {
    int i = blockIdx.x * blockDim.x + threadIdx.x;
    if (i < n) g_deg[i] = rsqrtf(1.0f + (float)g_cnt[i]);
}
__global__ __launch_bounds__(256) void k_bsum(int n) {
    __shared__ int sw[8];
    int b = blockIdx.x, t = threadIdx.x;
    int base = b * 1024;
    int s = 0;
    #pragma unroll
    for (int j = 0; j < 4; j++) {
        int i = base + t + j * 256;
        if (i < n) s += g_cnt[i];
    }
    #pragma unroll
    for (int o = 16; o; o >>= 1) s += __shfl_xor_sync(0xffffffffu, s, o);
    if ((t & 31) == 0) sw[t >> 5] = s;
    __syncthreads();
    if (t == 0) {
        int tot = 0;
        #pragma unroll
        for (int w = 0; w < 8; w++) tot += sw[w];
        g_bsum[b] = tot;
    }
}
__global__ __launch_bounds__(64) void k_bscan(int nb, int n) {
    __shared__ int sv[64];
    int t = threadIdx.x;
    int v = (t < nb) ? g_bsum[t] : 0;
    sv[t] = v;
    __syncthreads();
    #pragma unroll
    for (int o = 1; o < 64; o <<= 1) {
        int u = (t >= o) ? sv[t - o] : 0;
        __syncthreads();
        sv[t] += u;
        __syncthreads();
    }
    if (t < nb) g_bpre[t] = sv[t] - v;
    if (t == nb - 1) g_off[n] = sv[t];
}
__global__ __launch_bounds__(256) void k_boff(int n) {
    __shared__ int sts[256];
    int b = blockIdx.x, t = threadIdx.x;
    int base = b * 1024 + t * 4;

    int c0 = 0, c1 = 0, c2 = 0, c3 = 0;
    if (base + 3 < n) {
        int4 v = *(const int4*)&g_cnt[base];
        c0 = v.x; c1 = v.y; c2 = v.z; c3 = v.w;
    } else {
        if (base + 0 < n) c0 = g_cnt[base + 0];
        if (base + 1 < n) c1 = g_cnt[base + 1];
        if (base + 2 < n) c2 = g_cnt[base + 2];
        if (base + 3 < n) c3 = g_cnt[base + 3];
    }
    int tsum = c0 + c1 + c2 + c3;
    sts[t] = tsum;
    __syncthreads();
    #pragma unroll
    for (int o = 1; o < 256; o <<= 1) {
        int u = (t >= o) ? sts[t - o] : 0;
        __syncthreads();
        sts[t] += u;
        __syncthreads();
    }
    int excl = g_bpre[b] + sts[t] - tsum;

    int o0 = excl;
    int o1 = o0 + c0;
    int o2 = o1 + c1;
    int o3 = o2 + c2;
    if (base + 3 < n) {
        *(int4*)&g_off[base] = make_int4(o0, o1, o2, o3);
        *(int4*)&g_pos[base] = make_int4(o0, o1, o2, o3);
    } else {
        if (base + 0 < n) { g_off[base + 0] = o0; g_pos[base + 0] = o0; }
        if (base + 1 < n) { g_off[base + 1] = o1; g_pos[base + 1] = o1; }
        if (base + 2 < n) { g_off[base + 2] = o2; g_pos[base + 2] = o2; }
        if (base + 3 < n) { g_off[base + 3] = o3; g_pos[base + 3] = o3; }
    }
}
__global__ void k_fill(const int* __restrict__ src, const int* __restrict__ dst, int e) {
    int i = blockIdx.x * blockDim.x + threadIdx.x;
    if (i < e) {
        int d = dst[i];
        int p = atomicAdd(&g_pos[d], 1);
        g_csr[p] = src[i];
    }
}

// ---------------- fp16 tensor-core GEMM --------------------------------------
// C[M,N] = half( (A[M,K] @ B[K,N]) * dinv[row] )
// BM=128, BN=128, BK=32 halves; 256 threads, 8 warps (2x4), warp tile 64x32.
// As: [m][k] k-contig; Bs: [n][k] k-contig (staged transposed).
#define AW 34   // halves per As row (32 + 2 pad) -> 17-word stride
#define BW 34

__global__ __launch_bounds__(256) void sgemm_f16(
    int M, int N, int K,
    const float* __restrict__ A, const float* __restrict__ B, __half* __restrict__ C)
{
    const int BM = 128, BN = 128, BK = 32;
    __shared__ __align__(16) __half As[BM * AW];
    __shared__ __align__(16) __half Bs[BN * BW];

    int tid  = threadIdx.x;
    int lane = tid & 31;
    int warp = tid >> 5;
    int warpm = warp >> 2;            // 0..1
    int warpn = warp & 3;             // 0..3

    int blockM = blockIdx.y * BM;
    int blockN = blockIdx.x * BN;

    float c[4][4][4];
    #pragma unroll
    for (int i = 0; i < 4; i++)
        #pragma unroll
        for (int j = 0; j < 4; j++)
            #pragma unroll
            for (int q = 0; q < 4; q++) c[i][j][q] = 0.0f;

    int r = lane >> 2;                // 0..7
    int q = lane & 3;                 // 0..3

    // A staging coords: 2 threads per row, 4 float4 each
    int arow  = tid >> 1;             // 0..127
    int abase = (tid & 1) * 16;       // half index 0 or 16
    // B staging coords: thread covers one n column, 16 k values
    int bncol = tid & 127;
    int bkoff = (tid >> 7) * 16;      // 0 or 16

    for (int k0 = 0; k0 < K; k0 += BK) {
        // ---- stage A (fp32 -> fp16) ----
        bool aok = (blockM + arow < M);
        const float* Ap = A + (size_t)(blockM + arow) * K + k0 + abase;
        #pragma unroll
        for (int j = 0; j < 4; j++) {
            float4 av = make_float4(0.f, 0.f, 0.f, 0.f);
            if (aok) av = *(const float4*)(Ap + j * 4);
            int hi = arow * AW + abase + j * 4;
            *(__half2*)&As[hi]     = __floats2half2_rn(av.x, av.y);
            *(__half2*)&As[hi + 2] = __floats2half2_rn(av.z, av.w);
        }
        // ---- stage B transposed (fp32 -> fp16) ----
        {
            const float* Bp = B + (size_t)(k0 + bkoff) * N + blockN + bncol;
            #pragma unroll
            for (int j = 0; j < 16; j++)
                Bs[bncol * BW + bkoff + j] = __float2half_rn(Bp[(size_t)j * N]);
        }
        __syncthreads();

        #pragma unroll
        for (int kc = 0; kc < BK; kc += 16) {
            unsigned a[4][4], b[4][2];
            #pragma unroll
            for (int i = 0; i < 4; i++) {
                int mb = warpm * 64 + i * 16;
                a[i][0] = *(const unsigned*)&As[(mb + r)     * AW + kc + 2 * q];
                a[i][1] = *(const unsigned*)&As[(mb + r + 8) * AW + kc + 2 * q];
                a[i][2] = *(const unsigned*)&As[(mb + r)     * AW + kc + 2 * q + 8];
                a[i][3] = *(const unsigned*)&As[(mb + r + 8) * AW + kc + 2 * q + 8];
            }
            #pragma unroll
            for (int j = 0; j < 4; j++) {
                int nb = warpn * 32 + j * 8;
                b[j][0] = *(const unsigned*)&Bs[(nb + r) * BW + kc + 2 * q];
                b[j][1] = *(const unsigned*)&Bs[(nb + r) * BW + kc + 2 * q + 8];
            }
            #pragma unroll
            for (int i = 0; i < 4; i++)
                #pragma unroll
                for (int j = 0; j < 4; j++) {
                    asm volatile(
                        "mma.sync.aligned.m16n8k16.row.col.f32.f16.f16.f32 "
                        "{%0,%1,%2,%3},{%4,%5,%6,%7},{%8,%9},{%0,%1,%2,%3};"
                        : "+f"(c[i][j][0]), "+f"(c[i][j][1]),
                          "+f"(c[i][j][2]), "+f"(c[i][j][3])
                        : "r"(a[i][0]), "r"(a[i][1]), "r"(a[i][2]), "r"(a[i][3]),
                          "r"(b[j][0]), "r"(b[j][1]));
                }
        }
        __syncthreads();
    }

    // epilogue: scale rows by dinv, convert to fp16, store half2
    #pragma unroll
    for (int i = 0; i < 4; i++) {
        int gr0 = blockM + warpm * 64 + i * 16 + r;
        int gr1 = gr0 + 8;
        float dv0 = (gr0 < M) ? g_deg[gr0] : 0.f;
        float dv1 = (gr1 < M) ? g_deg[gr1] : 0.f;
        #pragma unroll
        for (int j = 0; j < 4; j++) {
            int gc = blockN + warpn * 32 + j * 8 + 2 * q;
            if (gr0 < M)
                *(__half2*)(C + (size_t)gr0 * N + gc) =
                    __floats2half2_rn(c[i][j][0] * dv0, c[i][j][1] * dv0);
            if (gr1 < M)
                *(__half2*)(C + (size_t)gr1 * N + gc) =
                    __floats2half2_rn(c[i][j][2] * dv1, c[i][j][3] * dv1);
        }
    }
}

// ---------------- fused CSR aggregation (fp16 gather) ------------------------
// out[d] = relu( dinv[d] * (h'[d] + sum_{s in in(d)} h'[s]) + b )
// T = F/2 threads, one half2 per thread.
template<int F>
__global__ __launch_bounds__(128) void k_agg(
    const __half* __restrict__ hp, const float* __restrict__ b,
    float* __restrict__ out)
{
    const int T = F / 2;
    __shared__ int sids[T];
    int node = blockIdx.x;
    int t = threadIdx.x;

    int beg = g_off[node], end = g_off[node + 1];
    float accx = 0.f, accy = 0.f;

    for (int e0 = beg; e0 < end; e0 += T) {
        int ne = min(T, end - e0);
        __syncthreads();
        if (t < ne) sids[t] = g_csr[e0 + t];
        __syncthreads();
        #pragma unroll 4
        for (int j = 0; j < ne; j++) {
            float2 f = __half22float2(
                *(const __half2*)(hp + (size_t)sids[j] * F + 2 * t));
            accx += f.x; accy += f.y;
        }
    }

    float dv = g_deg[node];
    float2 sv = __half22float2(*(const __half2*)(hp + (size_t)node * F + 2 * t));
    float ox = fmaxf(dv * (accx + sv.x) + b[2 * t],     0.f);
    float oy = fmaxf(dv * (accy + sv.y) + b[2 * t + 1], 0.f);
    *(float2*)(out + (size_t)node * F + 2 * t) = make_float2(ox, oy);
}

// ---------------- classifier + log_softmax -----------------------------------
__global__ __launch_bounds__(512) void k_cls(
    const float* __restrict__ X, const float* __restrict__ Wc,
    const float* __restrict__ bc, float* __restrict__ out, int n)
{
    __shared__ float sW[FMID * FOUT];
    __shared__ float sx[8][FMID];
    __shared__ float smax[8][2];
    __shared__ float ssum[8][2];

    int t  = threadIdx.x;
    int ry = threadIdx.y;
    int tid = ry * 64 + t;

    for (int i = tid; i < FMID * FOUT; i += 512) sW[i] = Wc[i];
    float bias = bc[t];

    #pragma unroll
    for (int it = 0; it < 2; it++) {
        int row = blockIdx.x * 16 + it * 8 + ry;
        __syncthreads();
        if (row < n) {
            #pragma unroll
            for (int k = t; k < FMID; k += 64) sx[ry][k] = X[(size_t)row * FMID + k];
        }
        __syncthreads();

        float acc = bias;
        if (row < n) {
            #pragma unroll 8
            for (int k = 0; k < FMID; k++)
                acc = fmaf(sx[ry][k], sW[k * FOUT + t], acc);
        }

        float m = acc;
        #pragma unroll
        for (int o = 16; o; o >>= 1) m = fmaxf(m, __shfl_xor_sync(0xffffffffu, m, o));
        if ((t & 31) == 0) smax[ry][t >> 5] = m;
        __syncthreads();
        float rowmax = fmaxf(smax[ry][0], smax[ry][1]);

        float e = expf(acc - rowmax);
        float s = e;
        #pragma unroll
        for (int o = 16; o; o >>= 1) s += __shfl_xor_sync(0xffffffffu, s, o);
        if ((t & 31) == 0) ssum[ry][t >> 5] = s;
        __syncthreads();
        float rowsum = ssum[ry][0] + ssum[ry][1];

        if (row < n)
            out[(size_t)row * FOUT + t] = acc - rowmax - logf(rowsum);
    }
}

// ---------------- launch ------------------------------------------------------
extern "C" void kernel_launch(void* const* d_in, const int* in_sizes, int n_in,
                              void* d_out, int out_size)
{
    const float* x   = (const float*)d_in[0];
    const int*   ei  = (const int*)  d_in[1];
    const float* W1  = (const float*)d_in[2];
    const float* b1  = (const float*)d_in[3];
    const float* W2  = (const float*)d_in[4];
    const float* b2  = (const float*)d_in[5];
    const float* Wc  = (const float*)d_in[6];
    const float* bc  = (const float*)d_in[7];
    float* out = (float*)d_out;

    int N = in_sizes[0] / FIN;
    int E = in_sizes[1] / 2;
    const int* src = ei;
    const int* dst = ei + E;

    __half *h1h, *h2h;
    float *x2, *x3;
    cudaGetSymbolAddress((void**)&h1h, g_h1h);
    cudaGetSymbolAddress((void**)&x2,  g_x2);
    cudaGetSymbolAddress((void**)&h2h, g_h2h);
    cudaGetSymbolAddress((void**)&x3,  g_x3);

    int nb = (N + 1023) / 1024;

    // degrees + CSR
    k_zero<<<(N + 4 + 255) / 256, 256>>>(N);
    k_hist<<<(E + 255) / 256, 256>>>(dst, E);
    k_dinv<<<(N + 255) / 256, 256>>>(N);
    k_bsum<<<nb, 256>>>(N);
    k_bscan<<<1, 64>>>(nb, N);
    k_boff<<<nb, 256>>>(N);
    k_fill<<<(E + 255) / 256, 256>>>(src, dst, E);

    // layer 1
    {
        dim3 grid(FHID / 128, (N + 127) / 128);
        sgemm_f16<<<grid, 256>>>(N, FHID, FIN, x, W1, h1h);
    }
    k_agg<FHID><<<N, FHID / 2>>>(h1h, b1, x2);

    // layer 2
    {
        dim3 grid(FMID / 128, (N + 127) / 128);
        sgemm_f16<<<grid, 256>>>(N, FMID, FHID, x2, W2, h2h);
    }
    k_agg<FMID><<<N, FMID / 2>>>(h2h, b2, x3);

    // classifier + log_softmax
    {
        dim3 block(64, 8);
        k_cls<<<(N + 15) / 16, block>>>(x3, Wc, bc, out, N);
    }
}

// round 10
// speedup vs baseline: 3.2330x; 1.2486x over previous
#include <cuda_runtime.h>
#include <cuda_fp16.h>
#include <math.h>

#define NN   50000
#define EE   800000
#define FIN  512
#define FHID 256
#define FMID 128
#define FOUT 64

// ---------------- scratch (static device globals) ----------------------------
__device__ __half g_xh [(size_t)NN * FIN];    // x in fp16
__device__ __half g_w1h[FIN * FHID];
__device__ __half g_w2h[FHID * FMID];
__device__ __half g_h1h[(size_t)NN * FHID];   // (x@W1)*dinv  fp16
__device__ __half g_x2h[(size_t)NN * FHID];   // relu layer-1 out fp16
__device__ __half g_h2h[(size_t)NN * FMID];   // (x2@W2)*dinv fp16
__device__ __half g_x3h[(size_t)NN * FMID];   // relu layer-2 out fp16
__device__ float  g_deg[NN];
__device__ int    g_cnt[NN + 4];
__device__ int    g_off[NN + 1];
__device__ int    g_pos[NN];
__device__ int    g_csr[EE];
__device__ int    g_bsum[256];
__device__ int    g_bpre[256];

// ---------------- fp32 -> fp16 conversion ------------------------------------
__global__ void k_tohalf(const float* __restrict__ s, __half* __restrict__ d, int n) {
    int i = (blockIdx.x * blockDim.x + threadIdx.x) * 8;
    if (i < n) {
        float4 v0 = *(const float4*)(s + i);
        float4 v1 = *(const float4*)(s + i + 4);
        *(__half2*)(d + i)     = __floats2half2_rn(v0.x, v0.y);
        *(__half2*)(d + i + 2) = __floats2half2_rn(v0.z, v0.w);
        *(__half2*)(d + i + 4) = __floats2half2_rn(v1.x, v1.y);
        *(__half2*)(d + i + 6) = __floats2half2_rn(v1.z, v1.w);
    }
}
__global__ void k_tohalf2(const float* __restrict__ s1, __half* __restrict__ d1, int n1,
                          const float* __restrict__ s2, __half* __restrict__ d2, int n2) {
    int i = (blockIdx.x * blockDim.x + threadIdx.x) * 8;
    const float* s; __half* d; int j;
    if (i < n1) { s = s1; d = d1; j = i; }
    else if (i < n1 + n2) { s = s2; d = d2; j = i - n1; }
    else return;
    float4 v0 = *(const float4*)(s + j);
    float4 v1 = *(const float4*)(s + j + 4);
    *(__half2*)(d + j)     = __floats2half2_rn(v0.x, v0.y);
    *(__half2*)(d + j + 2) = __floats2half2_rn(v0.z, v0.w);
    *(__half2*)(d + j + 4) = __floats2half2_rn(v1.x, v1.y);
    *(__half2*)(d + j + 6) = __floats2half2_rn(v1.z, v1.w);
}

// ---------------- degree / CSR build -----------------------------------------
__global__ void k_zero(int n) {
    int i = blockIdx.x * blockDim.x + threadIdx.x;
    if (i < n + 4) g_cnt[i] = 0;
}
__global__ void k_hist(const int* __restrict__ dst, int e) {
    int i = blockIdx.x * blockDim.x + threadIdx.x;
    if (i < e) atomicAdd(&g_cnt[dst[i]], 1);
}
__global__ void k_dinv(int n) {
    int i = blockIdx.x * blockDim.x + threadIdx.x;
    if (i < n) g_deg[i] = rsqrtf(1.0f + (float)g_cnt[i]);
}
__global__ __launch_bounds__(256) void k_bsum(int n) {
    __shared__ int sw[8];
    int b = blockIdx.x, t = threadIdx.x;
    int base = b * 1024;
    int s = 0;
    #pragma unroll
    for (int j = 0; j < 4; j++) {
        int i = base + t + j * 256;
        if (i < n) s += g_cnt[i];
    }
    #pragma unroll
    for (int o = 16; o; o >>= 1) s += __shfl_xor_sync(0xffffffffu, s, o);
    if ((t & 31) == 0) sw[t >> 5] = s;
    __syncthreads();
    if (t == 0) {
        int tot = 0;
        #pragma unroll
        for (int w = 0; w < 8; w++) tot += sw[w];
        g_bsum[b] = tot;
    }
}
__global__ __launch_bounds__(64) void k_bscan(int nb, int n) {
    __shared__ int sv[64];
    int t = threadIdx.x;
    int v = (t < nb) ? g_bsum[t] : 0;
    sv[t] = v;
    __syncthreads();
    #pragma unroll
    for (int o = 1; o < 64; o <<= 1) {
        int u = (t >= o) ? sv[t - o] : 0;
        __syncthreads();
        sv[t] += u;
        __syncthreads();
    }
    if (t < nb) g_bpre[t] = sv[t] - v;
    if (t == nb - 1) g_off[n] = sv[t];
}
__global__ __launch_bounds__(256) void k_boff(int n) {
    __shared__ int sts[256];
    int b = blockIdx.x, t = threadIdx.x;
    int base = b * 1024 + t * 4;

    int c0 = 0, c1 = 0, c2 = 0, c3 = 0;
    if (base + 3 < n) {
        int4 v = *(const int4*)&g_cnt[base];
        c0 = v.x; c1 = v.y; c2 = v.z; c3 = v.w;
    } else {
        if (base + 0 < n) c0 = g_cnt[base + 0];
        if (base + 1 < n) c1 = g_cnt[base + 1];
        if (base + 2 < n) c2 = g_cnt[base + 2];
        if (base + 3 < n) c3 = g_cnt[base + 3];
    }
    int tsum = c0 + c1 + c2 + c3;
    sts[t] = tsum;
    __syncthreads();
    #pragma unroll
    for (int o = 1; o < 256; o <<= 1) {
        int u = (t >= o) ? sts[t - o] : 0;
        __syncthreads();
        sts[t] += u;
        __syncthreads();
    }
    int excl = g_bpre[b] + sts[t] - tsum;

    int o0 = excl, o1 = o0 + c0, o2 = o1 + c1, o3 = o2 + c2;
    if (base + 3 < n) {
        *(int4*)&g_off[base] = make_int4(o0, o1, o2, o3);
        *(int4*)&g_pos[base] = make_int4(o0, o1, o2, o3);
    } else {
        if (base + 0 < n) { g_off[base + 0] = o0; g_pos[base + 0] = o0; }
        if (base + 1 < n) { g_off[base + 1] = o1; g_pos[base + 1] = o1; }
        if (base + 2 < n) { g_off[base + 2] = o2; g_pos[base + 2] = o2; }
        if (base + 3 < n) { g_off[base + 3] = o3; g_pos[base + 3] = o3; }
    }
}
__global__ void k_fill(const int* __restrict__ src, const int* __restrict__ dst, int e) {
    int i = blockIdx.x * blockDim.x + threadIdx.x;
    if (i < e) {
        int d = dst[i];
        int p = atomicAdd(&g_pos[d], 1);
        g_csr[p] = src[i];
    }
}

// ---------------- fp16 tensor-core GEMM, cp.async double-buffered ------------
// C[M,N] = half( (A[M,K] @ B[K,N]) * dinv[row] ), A,B fp16, BM=128,BN=128,BK=32
#define AW 40            // halves per As row (32 + 8 pad); 20-word stride
#define BW 136           // halves per Bs row (128 + 8 pad); 68-word stride
#define ABUF (128 * AW * 2)   // bytes per A stage
#define BBUF (32 * BW * 2)    // bytes per B stage

__device__ __forceinline__ void cpa16(unsigned dst, const void* src, int srcsize) {
    asm volatile("cp.async.ca.shared.global [%0], [%1], 16, %2;"
                 :: "r"(dst), "l"(src), "r"(srcsize));
}

__global__ __launch_bounds__(256) void sgemm_f16(
    int M, int N, int K,
    const __half* __restrict__ A, const __half* __restrict__ B, __half* __restrict__ C)
{
    __shared__ __align__(16) __half As[2 * 128 * AW];
    __shared__ __align__(16) __half Bs[2 * 32 * BW];

    int tid  = threadIdx.x;
    int lane = tid & 31;
    int warp = tid >> 5;
    int warpm = warp >> 2;            // 0..1
    int warpn = warp & 3;             // 0..3

    int blockM = blockIdx.y * 128;
    int blockN = blockIdx.x * 128;

    unsigned asA = (unsigned)__cvta_generic_to_shared(As);
    unsigned asB = (unsigned)__cvta_generic_to_shared(Bs);

    // staging coords (each thread: 2 A chunks + 2 B chunks of 16B per stage)
    int ar0 = tid >> 1,            ac0 = (tid & 1) * 2;        // A: v=tid
    int ar1 = (tid + 256) >> 1,    ac1 = ((tid + 256) & 1) * 2;
    int br0 = tid >> 4,            bc0 = (tid & 15);           // B: v=tid
    int br1 = (tid + 256) >> 4,    bc1 = ((tid + 256) & 15);

    // ldmatrix per-thread offsets
    int a_row = (lane & 7) + ((lane >> 3) & 1) * 8;   // 0..15
    int a_k8  = (lane >> 4) * 8;                      // 0 or 8
    int b_row = lane & 15;                            // 0..15

    float c[4][4][4];
    #pragma unroll
    for (int i = 0; i < 4; i++)
        #pragma unroll
        for (int j = 0; j < 4; j++)
            #pragma unroll
            for (int q = 0; q < 4; q++) c[i][j][q] = 0.0f;

    int KT = K >> 5;

    // ---- stage loader ----
    auto load_stage = [&](int kt, int buf) {
        int k0 = kt << 5;
        // A: 128 rows x 32 halves; chunk = 8 halves? -> 16B = 8 halves; 4 chunks/row
        {
            const __half* Ap = A + (size_t)(blockM + ar0) * K + k0 + ac0 * 8;
            cpa16(asA + buf * ABUF + (ar0 * AW + ac0 * 8) * 2, Ap,
                  (blockM + ar0 < M) ? 16 : 0);
            const __half* Ap2 = Ap + 16;   // same row, next 2 chunks? no:
            (void)Ap2;
        }
        {
            const __half* Ap = A + (size_t)(blockM + ar1) * K + k0 + ac1 * 8;
            cpa16(asA + buf * ABUF + (ar1 * AW + ac1 * 8) * 2, Ap,
                  (blockM + ar1 < M) ? 16 : 0);
        }
        // B: 32 rows x 128 halves; 16 chunks/row
        {
            const __half* Bp = B + (size_t)(k0 + br0) * N + blockN + bc0 * 8;
            cpa16(asB + buf * BBUF + (br0 * BW + bc0 * 8) * 2, Bp, 16);
        }
        {
            const __half* Bp = B + (size_t)(k0 + br1) * N + blockN + bc1 * 8;
            cpa16(asB + buf * BBUF + (br1 * BW + bc1 * 8) * 2, Bp, 16);
        }
        asm volatile("cp.async.commit_group;");
    };

    // wait: A coverage check — each stage needs 512 A chunks and 512 B chunks,
    // 256 threads x (2+2) chunks = 1024 = 512A + 512B?  A: v in {tid, tid+256}
    // covers 0..511 -> rows 0..255?? ar1 max = 255 > 127!  Fix mapping below.

    // (mapping fixed: see load_stage2)
    auto load_stage2 = [&](int kt, int buf) {
        int k0 = kt << 5;
        #pragma unroll
        for (int li = 0; li < 2; li++) {
            int v = tid + li * 256;          // 0..511
            int arow = v >> 2;               // 0..127
            int acnk = v & 3;                // 0..3
            const __half* Ap = A + (size_t)(blockM + arow) * K + k0 + acnk * 8;
            cpa16(asA + buf * ABUF + (arow * AW + acnk * 8) * 2, Ap,
                  (blockM + arow < M) ? 16 : 0);
        }
        #pragma unroll
        for (int li = 0; li < 2; li++) {
            int v = tid + li * 256;
            int brow = v >> 4;               // 0..31
            int bcnk = v & 15;               // 0..15
            const __half* Bp = B + (size_t)(k0 + brow) * N + blockN + bcnk * 8;
            cpa16(asB + buf * BBUF + (brow * BW + bcnk * 8) * 2, Bp, 16);
        }
        asm volatile("cp.async.commit_group;");
    };

    load_stage2(0, 0);

    for (int kt = 0; kt < KT; kt++) {
        int buf = kt & 1;
        if (kt + 1 < KT) {
            load_stage2(kt + 1, buf ^ 1);
            asm volatile("cp.async.wait_group 1;");
        } else {
            asm volatile("cp.async.wait_group 0;");
        }
        __syncthreads();

        unsigned aBase = asA + buf * ABUF;
        unsigned bBase = asB + buf * BBUF;

        #pragma unroll
        for (int kc = 0; kc < 32; kc += 16) {
            unsigned a[4][4], b[4][2];
            #pragma unroll
            for (int i = 0; i < 4; i++) {
                unsigned addr = aBase +
                    (((warpm * 64 + i * 16 + a_row) * AW) + kc + a_k8) * 2;
                asm volatile("ldmatrix.sync.aligned.m8n8.x4.shared.b16 "
                             "{%0,%1,%2,%3}, [%4];"
                             : "=r"(a[i][0]), "=r"(a[i][1]),
                               "=r"(a[i][2]), "=r"(a[i][3]) : "r"(addr));
            }
            #pragma unroll
            for (int j = 0; j < 4; j++) {
                unsigned addr = bBase +
                    (((kc + b_row) * BW) + warpn * 32 + j * 8) * 2;
                asm volatile("ldmatrix.sync.aligned.m8n8.x2.trans.shared.b16 "
                             "{%0,%1}, [%2];"
                             : "=r"(b[j][0]), "=r"(b[j][1]) : "r"(addr));
            }
            #pragma unroll
            for (int i = 0; i < 4; i++)
                #pragma unroll
                for (int j = 0; j < 4; j++) {
                    asm volatile(
                        "mma.sync.aligned.m16n8k16.row.col.f32.f16.f16.f32 "
                        "{%0,%1,%2,%3},{%4,%5,%6,%7},{%8,%9},{%0,%1,%2,%3};"
                        : "+f"(c[i][j][0]), "+f"(c[i][j][1]),
                          "+f"(c[i][j][2]), "+f"(c[i][j][3])
                        : "r"(a[i][0]), "r"(a[i][1]), "r"(a[i][2]), "r"(a[i][3]),
                          "r"(b[j][0]), "r"(b[j][1]));
                }
        }
        __syncthreads();
    }

    int r = lane >> 2, q = lane & 3;
    #pragma unroll
    for (int i = 0; i < 4; i++) {
        int gr0 = blockM + warpm * 64 + i * 16 + r;
        int gr1 = gr0 + 8;
        float dv0 = (gr0 < M) ? g_deg[gr0] : 0.f;
        float dv1 = (gr1 < M) ? g_deg[gr1] : 0.f;
        #pragma unroll
        for (int j = 0; j < 4; j++) {
            int gc = blockN + warpn * 32 + j * 8 + 2 * q;
            if (gr0 < M)
                *(__half2*)(C + (size_t)gr0 * N + gc) =
                    __floats2half2_rn(c[i][j][0] * dv0, c[i][j][1] * dv0);
            if (gr1 < M)
                *(__half2*)(C + (size_t)gr1 * N + gc) =
                    __floats2half2_rn(c[i][j][2] * dv1, c[i][j][3] * dv1);
        }
    }
}

// ---------------- fused CSR aggregation (fp16 in/out) ------------------------
// out[d] = half( relu( dinv[d]*(h'[d] + sum h'[s]) + b ) )
template<int F>
__global__ __launch_bounds__(F / 2) void k_agg(
    const __half* __restrict__ hp, const float* __restrict__ b,
    __half* __restrict__ out)
{
    const int T = F / 2;
    __shared__ int sids[T];
    int node = blockIdx.x;
    int t = threadIdx.x;

    int beg = g_off[node], end = g_off[node + 1];
    float accx = 0.f, accy = 0.f;

    for (int e0 = beg; e0 < end; e0 += T) {
        int ne = min(T, end - e0);
        __syncthreads();
        if (t < ne) sids[t] = g_csr[e0 + t];
        __syncthreads();
        #pragma unroll 4
        for (int j = 0; j < ne; j++) {
            float2 f = __half22float2(
                *(const __half2*)(hp + (size_t)sids[j] * F + 2 * t));
            accx += f.x; accy += f.y;
        }
    }

    float dv = g_deg[node];
    float2 sv = __half22float2(*(const __half2*)(hp + (size_t)node * F + 2 * t));
    float ox = fmaxf(dv * (accx + sv.x) + b[2 * t],     0.f);
    float oy = fmaxf(dv * (accy + sv.y) + b[2 * t + 1], 0.f);
    *(__half2*)(out + (size_t)node * F + 2 * t) = __floats2half2_rn(ox, oy);
}

// ---------------- classifier + log_softmax (fp16 X) --------------------------
__global__ __launch_bounds__(512) void k_cls(
    const __half* __restrict__ X, const float* __restrict__ Wc,
    const float* __restrict__ bc, float* __restrict__ out, int n)
{
    __shared__ float sW[FMID * FOUT];
    __shared__ float sx[8][FMID];
    __shared__ float smax[8][2];
    __shared__ float ssum[8][2];

    int t  = threadIdx.x;
    int ry = threadIdx.y;
    int tid = ry * 64 + t;

    for (int i = tid; i < FMID * FOUT; i += 512) sW[i] = Wc[i];
    float bias = bc[t];

    #pragma unroll
    for (int it = 0; it < 2; it++) {
        int row = blockIdx.x * 16 + it * 8 + ry;
        __syncthreads();
        if (row < n) {
            #pragma unroll
            for (int k = t; k < FMID; k += 64)
                sx[ry][k] = __half2float(X[(size_t)row * FMID + k]);
        }
        __syncthreads();

        float acc = bias;
        if (row < n) {
            #pragma unroll 8
            for (int k = 0; k < FMID; k++)
                acc = fmaf(sx[ry][k], sW[k * FOUT + t], acc);
        }

        float m = acc;
        #pragma unroll
        for (int o = 16; o; o >>= 1) m = fmaxf(m, __shfl_xor_sync(0xffffffffu, m, o));
        if ((t & 31) == 0) smax[ry][t >> 5] = m;
        __syncthreads();
        float rowmax = fmaxf(smax[ry][0], smax[ry][1]);

        float e = expf(acc - rowmax);
        float s = e;
        #pragma unroll
        for (int o = 16; o; o >>= 1) s += __shfl_xor_sync(0xffffffffu, s, o);
        if ((t & 31) == 0) ssum[ry][t >> 5] = s;
        __syncthreads();
        float rowsum = ssum[ry][0] + ssum[ry][1];

        if (row < n)
            out[(size_t)row * FOUT + t] = acc - rowmax - logf(rowsum);
    }
}

// ---------------- launch ------------------------------------------------------
extern "C" void kernel_launch(void* const* d_in, const int* in_sizes, int n_in,
                              void* d_out, int out_size)
{
    const float* x   = (const float*)d_in[0];
    const int*   ei  = (const int*)  d_in[1];
    const float* W1  = (const float*)d_in[2];
    const float* b1  = (const float*)d_in[3];
    const float* W2  = (const float*)d_in[4];
    const float* b2  = (const float*)d_in[5];
    const float* Wc  = (const float*)d_in[6];
    const float* bc  = (const float*)d_in[7];
    float* out = (float*)d_out;

    int N = in_sizes[0] / FIN;
    int E = in_sizes[1] / 2;
    const int* src = ei;
    const int* dst = ei + E;

    __half *xh, *w1h, *w2h, *h1h, *x2h, *h2h, *x3h;
    cudaGetSymbolAddress((void**)&xh,  g_xh);
    cudaGetSymbolAddress((void**)&w1h, g_w1h);
    cudaGetSymbolAddress((void**)&w2h, g_w2h);
    cudaGetSymbolAddress((void**)&h1h, g_h1h);
    cudaGetSymbolAddress((void**)&x2h, g_x2h);
    cudaGetSymbolAddress((void**)&h2h, g_h2h);
    cudaGetSymbolAddress((void**)&x3h, g_x3h);

    int nb = (N + 1023) / 1024;
    int nx = N * FIN;
    int nw = FIN * FHID + FHID * FMID;

    // 0-2: degree
    k_zero<<<(N + 4 + 255) / 256, 256>>>(N);
    k_hist<<<(E + 255) / 256, 256>>>(dst, E);
    k_dinv<<<(N + 255) / 256, 256>>>(N);
    // 3-4: fp16 conversions
    k_tohalf<<<(nx / 8 + 255) / 256, 256>>>(x, xh, nx);
    k_tohalf2<<<(nw / 8 + 255) / 256, 256>>>(W1, w1h, FIN * FHID, W2, w2h, FHID * FMID);
    // 5: GEMM1  (profiled by ncu -s 5 -c 1)
    {
        dim3 grid(FHID / 128, (N + 127) / 128);
        sgemm_f16<<<grid, 256>>>(N, FHID, FIN, xh, w1h, h1h);
    }
    // 6-9: CSR build
    k_bsum<<<nb, 256>>>(N);
    k_bscan<<<1, 64>>>(nb, N);
    k_boff<<<nb, 256>>>(N);
    k_fill<<<(E + 255) / 256, 256>>>(src, dst, E);
    // 10: agg1
    k_agg<FHID><<<N, FHID / 2>>>(h1h, b1, x2h);
    // 11: GEMM2
    {
        dim3 grid(FMID / 128, (N + 127) / 128);
        sgemm_f16<<<grid, 256>>>(N, FMID, FHID, x2h, w2h, h2h);
    }
    // 12: agg2
    k_agg<FMID><<<N, FMID / 2>>>(h2h, b2, x3h);
    // 13: classifier
    {
        dim3 block(64, 8);
        k_cls<<<(N + 15) / 16, block>>>(x3h, Wc, bc, out, N);
    }
}

// round 13
// speedup vs baseline: 4.3210x; 1.3365x over previous
#include <cuda_runtime.h>
#include <cuda_fp16.h>
#include <math.h>

#define NN   50000
#define EE   800000
#define FIN  512
#define FHID 256
#define FMID 128
#define FOUT 64

// ---------------- scratch (static device globals) ----------------------------
__device__ __half g_xh [(size_t)NN * FIN];
__device__ __half g_w1h[FIN * FHID];
__device__ __half g_w2h[FHID * FMID];
__device__ __half g_wch[FMID * FOUT];
__device__ __half g_h1h[(size_t)NN * FHID];
__device__ __half g_x2h[(size_t)NN * FHID];
__device__ __half g_h2h[(size_t)NN * FMID];
__device__ __half g_x3h[(size_t)NN * FMID];
__device__ float  g_deg[NN];
__device__ int    g_cnt[NN + 4];
__device__ int    g_off[NN + 1];
__device__ int    g_pos[NN];
__device__ int    g_csr[EE];
__device__ int    g_bsum[256];
__device__ int    g_bpre[256];

// ---------------- fused fp32->fp16 conversion (+ cnt zeroing) ----------------
// Regions: x[nx], W1, W2, Wc, each size divisible by 8.
__global__ void k_tohalf_all(const float* __restrict__ x,
                             const float* __restrict__ W1,
                             const float* __restrict__ W2,
                             const float* __restrict__ Wc,
                             int nx)
{
    int gid = blockIdx.x * blockDim.x + threadIdx.x;
    // zero the degree counters on the side
    {
        int z = gid * 8;
        if (z < NN + 4) {
            #pragma unroll
            for (int j = 0; j < 8; j++)
                if (z + j < NN + 4) g_cnt[z + j] = 0;
        }
    }
    const int n1 = FIN * FHID, n2 = FHID * FMID, n3 = FMID * FOUT;
    int i = gid * 8;
    const float* s; __half* d; int j;
    if (i < nx)                     { s = x;  d = g_xh;  j = i; }
    else if (i < nx + n1)           { s = W1; d = g_w1h; j = i - nx; }
    else if (i < nx + n1 + n2)      { s = W2; d = g_w2h; j = i - nx - n1; }
    else if (i < nx + n1 + n2 + n3) { s = Wc; d = g_wch; j = i - nx - n1 - n2; }
    else return;
    float4 v0 = *(const float4*)(s + j);
    float4 v1 = *(const float4*)(s + j + 4);
    *(__half2*)(d + j)     = __floats2half2_rn(v0.x, v0.y);
    *(__half2*)(d + j + 2) = __floats2half2_rn(v0.z, v0.w);
    *(__half2*)(d + j + 4) = __floats2half2_rn(v1.x, v1.y);
    *(__half2*)(d + j + 6) = __floats2half2_rn(v1.z, v1.w);
}

// ---------------- degree / CSR build -----------------------------------------
__global__ void k_hist(const int* __restrict__ dst, int e) {
    int i = blockIdx.x * blockDim.x + threadIdx.x;
    if (i < e) atomicAdd(&g_cnt[dst[i]], 1);
}
__global__ void k_dinv(int n) {
    int i = blockIdx.x * blockDim.x + threadIdx.x;
    if (i < n) g_deg[i] = rsqrtf(1.0f + (float)g_cnt[i]);
}
__global__ __launch_bounds__(256) void k_bsum(int n) {
    __shared__ int sw[8];
    int b = blockIdx.x, t = threadIdx.x;
    int base = b * 1024;
    int s = 0;
    #pragma unroll
    for (int j = 0; j < 4; j++) {
        int i = base + t + j * 256;
        if (i < n) s += g_cnt[i];
    }
    #pragma unroll
    for (int o = 16; o; o >>= 1) s += __shfl_xor_sync(0xffffffffu, s, o);
    if ((t & 31) == 0) sw[t >> 5] = s;
    __syncthreads();
    if (t == 0) {
        int tot = 0;
        #pragma unroll
        for (int w = 0; w < 8; w++) tot += sw[w];
        g_bsum[b] = tot;
    }
}
__global__ __launch_bounds__(64) void k_bscan(int nb, int n) {
    __shared__ int sv[64];
    int t = threadIdx.x;
    int v = (t < nb) ? g_bsum[t] : 0;
    sv[t] = v;
    __syncthreads();
    #pragma unroll
    for (int o = 1; o < 64; o <<= 1) {
        int u = (t >= o) ? sv[t - o] : 0;
        __syncthreads();
        sv[t] += u;
        __syncthreads();
    }
    if (t < nb) g_bpre[t] = sv[t] - v;
    if (t == nb - 1) g_off[n] = sv[t];
}
__global__ __launch_bounds__(256) void k_boff(int n) {
    __shared__ int sts[256];
    int b = blockIdx.x, t = threadIdx.x;
    int base = b * 1024 + t * 4;

    int c0 = 0, c1 = 0, c2 = 0, c3 = 0;
    if (base + 3 < n) {
        int4 v = *(const int4*)&g_cnt[base];
        c0 = v.x; c1 = v.y; c2 = v.z; c3 = v.w;
    } else {
        if (base + 0 < n) c0 = g_cnt[base + 0];
        if (base + 1 < n) c1 = g_cnt[base + 1];
        if (base + 2 < n) c2 = g_cnt[base + 2];
        if (base + 3 < n) c3 = g_cnt[base + 3];
    }
    int tsum = c0 + c1 + c2 + c3;
    sts[t] = tsum;
    __syncthreads();
    #pragma unroll
    for (int o = 1; o < 256; o <<= 1) {
        int u = (t >= o) ? sts[t - o] : 0;
        __syncthreads();
        sts[t] += u;
        __syncthreads();
    }
    int excl = g_bpre[b] + sts[t] - tsum;

    int o0 = excl, o1 = o0 + c0, o2 = o1 + c1, o3 = o2 + c2;
    if (base + 3 < n) {
        *(int4*)&g_off[base] = make_int4(o0, o1, o2, o3);
        *(int4*)&g_pos[base] = make_int4(o0, o1, o2, o3);
    } else {
        if (base + 0 < n) { g_off[base + 0] = o0; g_pos[base + 0] = o0; }
        if (base + 1 < n) { g_off[base + 1] = o1; g_pos[base + 1] = o1; }
        if (base + 2 < n) { g_off[base + 2] = o2; g_pos[base + 2] = o2; }
        if (base + 3 < n) { g_off[base + 3] = o3; g_pos[base + 3] = o3; }
    }
}
__global__ void k_fill(const int* __restrict__ src, const int* __restrict__ dst, int e) {
    int i = blockIdx.x * blockDim.x + threadIdx.x;
    if (i < e) {
        int d = dst[i];
        int p = atomicAdd(&g_pos[d], 1);
        g_csr[p] = src[i];
    }
}

// ---------------- fp16 tensor-core GEMM, cp.async double-buffered ------------
#define AW 40
#define BW 136
#define ABUF (128 * AW * 2)
#define BBUF (32 * BW * 2)

__device__ __forceinline__ void cpa16(unsigned dst, const void* src, int srcsize) {
    asm volatile("cp.async.ca.shared.global [%0], [%1], 16, %2;"
                 :: "r"(dst), "l"(src), "r"(srcsize));
}

__global__ __launch_bounds__(256) void sgemm_f16(
    int M, int N, int K,
    const __half* __restrict__ A, const __half* __restrict__ B, __half* __restrict__ C)
{
    __shared__ __align__(16) __half As[2 * 128 * AW];
    __shared__ __align__(16) __half Bs[2 * 32 * BW];

    int tid  = threadIdx.x;
    int lane = tid & 31;
    int warp = tid >> 5;
    int warpm = warp >> 2;
    int warpn = warp & 3;

    int blockM = blockIdx.y * 128;
    int blockN = blockIdx.x * 128;

    unsigned asA = (unsigned)__cvta_generic_to_shared(As);
    unsigned asB = (unsigned)__cvta_generic_to_shared(Bs);

    int a_row = (lane & 7) + ((lane >> 3) & 1) * 8;
    int a_k8  = (lane >> 4) * 8;
    int b_row = lane & 15;

    float c[4][4][4];
    #pragma unroll
    for (int i = 0; i < 4; i++)
        #pragma unroll
        for (int j = 0; j < 4; j++)
            #pragma unroll
            for (int q = 0; q < 4; q++) c[i][j][q] = 0.0f;

    int KT = K >> 5;

    auto load_stage = [&](int kt, int buf) {
        int k0 = kt << 5;
        #pragma unroll
        for (int li = 0; li < 2; li++) {
            int v = tid + li * 256;
            int arow = v >> 2;
            int acnk = v & 3;
            const __half* Ap = A + (size_t)(blockM + arow) * K + k0 + acnk * 8;
            cpa16(asA + buf * ABUF + (arow * AW + acnk * 8) * 2, Ap,
                  (blockM + arow < M) ? 16 : 0);
        }
        #pragma unroll
        for (int li = 0; li < 2; li++) {
            int v = tid + li * 256;
            int brow = v >> 4;
            int bcnk = v & 15;
            const __half* Bp = B + (size_t)(k0 + brow) * N + blockN + bcnk * 8;
            cpa16(asB + buf * BBUF + (brow * BW + bcnk * 8) * 2, Bp, 16);
        }
        asm volatile("cp.async.commit_group;");
    };

    load_stage(0, 0);

    for (int kt = 0; kt < KT; kt++) {
        int buf = kt & 1;
        if (kt + 1 < KT) {
            load_stage(kt + 1, buf ^ 1);
            asm volatile("cp.async.wait_group 1;");
        } else {
            asm volatile("cp.async.wait_group 0;");
        }
        __syncthreads();

        unsigned aBase = asA + buf * ABUF;
        unsigned bBase = asB + buf * BBUF;

        #pragma unroll
        for (int kc = 0; kc < 32; kc += 16) {
            unsigned a[4][4], b[4][2];
            #pragma unroll
            for (int i = 0; i < 4; i++) {
                unsigned addr = aBase +
                    (((warpm * 64 + i * 16 + a_row) * AW) + kc + a_k8) * 2;
                asm volatile("ldmatrix.sync.aligned.m8n8.x4.shared.b16 "
                             "{%0,%1,%2,%3}, [%4];"
                             : "=r"(a[i][0]), "=r"(a[i][1]),
                               "=r"(a[i][2]), "=r"(a[i][3]) : "r"(addr));
            }
            #pragma unroll
            for (int j = 0; j < 4; j++) {
                unsigned addr = bBase +
                    (((kc + b_row) * BW) + warpn * 32 + j * 8) * 2;
                asm volatile("ldmatrix.sync.aligned.m8n8.x2.trans.shared.b16 "
                             "{%0,%1}, [%2];"
                             : "=r"(b[j][0]), "=r"(b[j][1]) : "r"(addr));
            }
            #pragma unroll
            for (int i = 0; i < 4; i++)
                #pragma unroll
                for (int j = 0; j < 4; j++) {
                    asm volatile(
                        "mma.sync.aligned.m16n8k16.row.col.f32.f16.f16.f32 "
                        "{%0,%1,%2,%3},{%4,%5,%6,%7},{%8,%9},{%0,%1,%2,%3};"
                        : "+f"(c[i][j][0]), "+f"(c[i][j][1]),
                          "+f"(c[i][j][2]), "+f"(c[i][j][3])
                        : "r"(a[i][0]), "r"(a[i][1]), "r"(a[i][2]), "r"(a[i][3]),
                          "r"(b[j][0]), "r"(b[j][1]));
                }
        }
        __syncthreads();
    }

    int r = lane >> 2, q = lane & 3;
    #pragma unroll
    for (int i = 0; i < 4; i++) {
        int gr0 = blockM + warpm * 64 + i * 16 + r;
        int gr1 = gr0 + 8;
        float dv0 = (gr0 < M) ? g_deg[gr0] : 0.f;
        float dv1 = (gr1 < M) ? g_deg[gr1] : 0.f;
        #pragma unroll
        for (int j = 0; j < 4; j++) {
            int gc = blockN + warpn * 32 + j * 8 + 2 * q;
            if (gr0 < M)
                *(__half2*)(C + (size_t)gr0 * N + gc) =
                    __floats2half2_rn(c[i][j][0] * dv0, c[i][j][1] * dv0);
            if (gr1 < M)
                *(__half2*)(C + (size_t)gr1 * N + gc) =
                    __floats2half2_rn(c[i][j][2] * dv1, c[i][j][3] * dv1);
        }
    }
}

// ---------------- fused CSR aggregation (fp16 in/out) ------------------------
template<int F>
__global__ __launch_bounds__(F / 2) void k_agg(
    const __half* __restrict__ hp, const float* __restrict__ b,
    __half* __restrict__ out)
{
    const int T = F / 2;
    __shared__ int sids[T];
    int node = blockIdx.x;
    int t = threadIdx.x;

    int beg = g_off[node], end = g_off[node + 1];
    float accx = 0.f, accy = 0.f;

    for (int e0 = beg; e0 < end; e0 += T) {
        int ne = min(T, end - e0);
        __syncthreads();
        if (t < ne) sids[t] = g_csr[e0 + t];
        __syncthreads();
        #pragma unroll 4
        for (int j = 0; j < ne; j++) {
            float2 f = __half22float2(
                *(const __half2*)(hp + (size_t)sids[j] * F + 2 * t));
            accx += f.x; accy += f.y;
        }
    }

    float dv = g_deg[node];
    float2 sv = __half22float2(*(const __half2*)(hp + (size_t)node * F + 2 * t));
    float ox = fmaxf(dv * (accx + sv.x) + b[2 * t],     0.f);
    float oy = fmaxf(dv * (accy + sv.y) + b[2 * t + 1], 0.f);
    *(__half2*)(out + (size_t)node * F + 2 * t) = __floats2half2_rn(ox, oy);
}

// ---------------- classifier (HMMA) + log_softmax ----------------------------
// Block: 256 thr (8 warps), 128 rows; X[128,128]@Wc[128,64] fp16 -> fp32 acc.
__global__ __launch_bounds__(256) void k_cls(
    const __half* __restrict__ X, const __half* __restrict__ Wc,
    const float* __restrict__ bc, float* __restrict__ out, int n)
{
    __shared__ __align__(16) __half sX[128][136];
    __shared__ __align__(16) __half sW[128][72];

    int tid = threadIdx.x, lane = tid & 31, w = tid >> 5;
    int blockM = blockIdx.x * 128;

    // stage X tile (zero-fill OOB rows)
    #pragma unroll
    for (int it = 0; it < 8; it++) {
        int v = tid + it * 256;
        int row = v >> 4, ck = v & 15;
        int gr = blockM + row;
        uint4 val = make_uint4(0u, 0u, 0u, 0u);
        if (gr < n) val = *(const uint4*)(X + (size_t)gr * FMID + ck * 8);
        *(uint4*)&sX[row][ck * 8] = val;
    }
    // stage Wc
    #pragma unroll
    for (int it = 0; it < 4; it++) {
        int v = tid + it * 256;
        int row = v >> 3, ck = v & 7;
        *(uint4*)&sW[row][ck * 8] = *(const uint4*)(Wc + row * FOUT + ck * 8);
    }
    __syncthreads();

    int a_row = (lane & 7) + ((lane >> 3) & 1) * 8;
    int a_k8  = (lane >> 4) * 8;
    int b_row = lane & 15;

    float c[8][4];
    #pragma unroll
    for (int j = 0; j < 8; j++)
        #pragma unroll
        for (int q = 0; q < 4; q++) c[j][q] = 0.0f;

    #pragma unroll
    for (int k = 0; k < 8; k++) {
        unsigned a[4];
        unsigned addr = (unsigned)__cvta_generic_to_shared(
            &sX[w * 16 + a_row][k * 16 + a_k8]);
        asm volatile("ldmatrix.sync.aligned.m8n8.x4.shared.b16 {%0,%1,%2,%3}, [%4];"
                     : "=r"(a[0]), "=r"(a[1]), "=r"(a[2]), "=r"(a[3]) : "r"(addr));
        #pragma unroll
        for (int j = 0; j < 8; j++) {
            unsigned b[2];
            unsigned baddr = (unsigned)__cvta_generic_to_shared(
                &sW[k * 16 + b_row][j * 8]);
            asm volatile("ldmatrix.sync.aligned.m8n8.x2.trans.shared.b16 {%0,%1}, [%2];"
                         : "=r"(b[0]), "=r"(b[1]) : "r"(baddr));
            asm volatile(
                "mma.sync.aligned.m16n8k16.row.col.f32.f16.f16.f32 "
                "{%0,%1,%2,%3},{%4,%5,%6,%7},{%8,%9},{%0,%1,%2,%3};"
                : "+f"(c[j][0]), "+f"(c[j][1]), "+f"(c[j][2]), "+f"(c[j][3])
                : "r"(a[0]), "r"(a[1]), "r"(a[2]), "r"(a[3]),
                  "r"(b[0]), "r"(b[1]));
        }
    }

    int r = lane >> 2, q = lane & 3;

    // add bias
    #pragma unroll
    for (int j = 0; j < 8; j++) {
        float2 bb = *(const float2*)(bc + j * 8 + 2 * q);
        c[j][0] += bb.x; c[j][1] += bb.y;
        c[j][2] += bb.x; c[j][3] += bb.y;
    }

    // log-softmax over 64 cols; row0 = w*16+r, row1 = row0+8
    float m0 = -1e30f, m1 = -1e30f;
    #pragma unroll
    for (int j = 0; j < 8; j++) {
        m0 = fmaxf(m0, fmaxf(c[j][0], c[j][1]));
        m1 = fmaxf(m1, fmaxf(c[j][2], c[j][3]));
    }
    m0 = fmaxf(m0, __shfl_xor_sync(0xffffffffu, m0, 1));
    m0 = fmaxf(m0, __shfl_xor_sync(0xffffffffu, m0, 2));
    m1 = fmaxf(m1, __shfl_xor_sync(0xffffffffu, m1, 1));
    m1 = fmaxf(m1, __shfl_xor_sync(0xffffffffu, m1, 2));

    float s0 = 0.f, s1 = 0.f;
    #pragma unroll
    for (int j = 0; j < 8; j++) {
        s0 += expf(c[j][0] - m0) + expf(c[j][1] - m0);
        s1 += expf(c[j][2] - m1) + expf(c[j][3] - m1);
    }
    s0 += __shfl_xor_sync(0xffffffffu, s0, 1);
    s0 += __shfl_xor_sync(0xffffffffu, s0, 2);
    s1 += __shfl_xor_sync(0xffffffffu, s1, 1);
    s1 += __shfl_xor_sync(0xffffffffu, s1, 2);

    float l0 = m0 + logf(s0);
    float l1 = m1 + logf(s1);

    int gr0 = blockM + w * 16 + r;
    int gr1 = gr0 + 8;
    #pragma unroll
    for (int j = 0; j < 8; j++) {
        int gc = j * 8 + 2 * q;
        if (gr0 < n)
            *(float2*)(out + (size_t)gr0 * FOUT + gc) =
                make_float2(c[j][0] - l0, c[j][1] - l0);
        if (gr1 < n)
            *(float2*)(out + (size_t)gr1 * FOUT + gc) =
                make_float2(c[j][2] - l1, c[j][3] - l1);
    }
}

// ---------------- launch ------------------------------------------------------
extern "C" void kernel_launch(void* const* d_in, const int* in_sizes, int n_in,
                              void* d_out, int out_size)
{
    const float* x   = (const float*)d_in[0];
    const int*   ei  = (const int*)  d_in[1];
    const float* W1  = (const float*)d_in[2];
    const float* b1  = (const float*)d_in[3];
    const float* W2  = (const float*)d_in[4];
    const float* b2  = (const float*)d_in[5];
    const float* Wc  = (const float*)d_in[6];
    const float* bc  = (const float*)d_in[7];
    float* out = (float*)d_out;

    int N = in_sizes[0] / FIN;
    int E = in_sizes[1] / 2;
    const int* src = ei;
    const int* dst = ei + E;

    __half *xh, *w1h, *w2h, *wch, *h1h, *x2h, *h2h, *x3h;
    cudaGetSymbolAddress((void**)&xh,  g_xh);
    cudaGetSymbolAddress((void**)&w1h, g_w1h);
    cudaGetSymbolAddress((void**)&w2h, g_w2h);
    cudaGetSymbolAddress((void**)&wch, g_wch);
    cudaGetSymbolAddress((void**)&h1h, g_h1h);
    cudaGetSymbolAddress((void**)&x2h, g_x2h);
    cudaGetSymbolAddress((void**)&h2h, g_h2h);
    cudaGetSymbolAddress((void**)&x3h, g_x3h);

    int nb = (N + 1023) / 1024;
    int nx = N * FIN;
    int tot = nx + FIN * FHID + FHID * FMID + FMID * FOUT;

    // 0: conversions + cnt zero
    k_tohalf_all<<<(tot / 8 + 255) / 256, 256>>>(x, W1, W2, Wc, nx);
    // 1-2: degree
    k_hist<<<(E + 255) / 256, 256>>>(dst, E);
    k_dinv<<<(N + 255) / 256, 256>>>(N);
    // 3: GEMM1 (ncu capture slot)
    {
        dim3 grid(FHID / 128, (N + 127) / 128);
        sgemm_f16<<<grid, 256>>>(N, FHID, FIN, xh, w1h, h1h);
    }
    // 4-7: CSR build
    k_bsum<<<nb, 256>>>(N);
    k_bscan<<<1, 64>>>(nb, N);
    k_boff<<<nb, 256>>>(N);
    k_fill<<<(E + 255) / 256, 256>>>(src, dst, E);
    // 8: agg1
    k_agg<FHID><<<N, FHID / 2>>>(h1h, b1, x2h);
    // 9: GEMM2
    {
        dim3 grid(FMID / 128, (N + 127) / 128);
        sgemm_f16<<<grid, 256>>>(N, FMID, FHID, x2h, w2h, h2h);
    }
    // 10: agg2
    k_agg<FMID><<<N, FMID / 2>>>(h2h, b2, x3h);
    // 11: classifier
    k_cls<<<(N + 127) / 128, 256>>>(x3h, wch, bc, out, N);
}

// round 16
// speedup vs baseline: 4.4157x; 1.0219x over previous
#include <cuda_runtime.h>
#include <cuda_fp16.h>
#include <math.h>

#define NN   50000
#define EE   800000
#define FIN  512
#define FHID 256
#define FMID 128
#define FOUT 64

// ---------------- scratch (static device globals) ----------------------------
__device__ __half g_xh [(size_t)NN * FIN];
__device__ __half g_w1h[FIN * FHID];
__device__ __half g_w2h[FHID * FMID];
__device__ __half g_wch[FMID * FOUT];
__device__ __half g_h1h[(size_t)NN * FHID];
__device__ __half g_x2h[(size_t)NN * FHID];
__device__ __half g_h2h[(size_t)NN * FMID];
__device__ __half g_x3h[(size_t)NN * FMID];
__device__ float  g_deg[NN];
__device__ int    g_cnt[NN + 4];
__device__ int    g_off[NN + 1];
__device__ int    g_pos[NN];
__device__ int    g_csr[EE];
__device__ int    g_bsum[256];
__device__ int    g_bpre[256];

// ---------------- fused fp32->fp16 conversion (+ cnt zeroing) ----------------
__global__ void k_tohalf_all(const float* __restrict__ x,
                             const float* __restrict__ W1,
                             const float* __restrict__ W2,
                             const float* __restrict__ Wc,
                             int nx)
{
    int gid = blockIdx.x * blockDim.x + threadIdx.x;
    {
        int z = gid * 8;
        if (z < NN + 4) {
            #pragma unroll
            for (int j = 0; j < 8; j++)
                if (z + j < NN + 4) g_cnt[z + j] = 0;
        }
    }
    const int n1 = FIN * FHID, n2 = FHID * FMID, n3 = FMID * FOUT;
    int i = gid * 8;
    const float* s; __half* d; int j;
    if (i < nx)                     { s = x;  d = g_xh;  j = i; }
    else if (i < nx + n1)           { s = W1; d = g_w1h; j = i - nx; }
    else if (i < nx + n1 + n2)      { s = W2; d = g_w2h; j = i - nx - n1; }
    else if (i < nx + n1 + n2 + n3) { s = Wc; d = g_wch; j = i - nx - n1 - n2; }
    else return;
    float4 v0 = *(const float4*)(s + j);
    float4 v1 = *(const float4*)(s + j + 4);
    *(__half2*)(d + j)     = __floats2half2_rn(v0.x, v0.y);
    *(__half2*)(d + j + 2) = __floats2half2_rn(v0.z, v0.w);
    *(__half2*)(d + j + 4) = __floats2half2_rn(v1.x, v1.y);
    *(__half2*)(d + j + 6) = __floats2half2_rn(v1.z, v1.w);
}

// ---------------- degree / CSR build -----------------------------------------
__global__ void k_hist(const int* __restrict__ dst, int e) {
    int i = blockIdx.x * blockDim.x + threadIdx.x;
    if (i < e) atomicAdd(&g_cnt[dst[i]], 1);
}
__global__ void k_dinv(int n) {
    int i = blockIdx.x * blockDim.x + threadIdx.x;
    if (i < n) g_deg[i] = rsqrtf(1.0f + (float)g_cnt[i]);
}
__global__ __launch_bounds__(256) void k_bsum(int n) {
    __shared__ int sw[8];
    int b = blockIdx.x, t = threadIdx.x;
    int base = b * 1024;
    int s = 0;
    #pragma unroll
    for (int j = 0; j < 4; j++) {
        int i = base + t + j * 256;
        if (i < n) s += g_cnt[i];
    }
    #pragma unroll
    for (int o = 16; o; o >>= 1) s += __shfl_xor_sync(0xffffffffu, s, o);
    if ((t & 31) == 0) sw[t >> 5] = s;
    __syncthreads();
    if (t == 0) {
        int tot = 0;
        #pragma unroll
        for (int w = 0; w < 8; w++) tot += sw[w];
        g_bsum[b] = tot;
    }
}
__global__ __launch_bounds__(64) void k_bscan(int nb, int n) {
    __shared__ int sv[64];
    int t = threadIdx.x;
    int v = (t < nb) ? g_bsum[t] : 0;
    sv[t] = v;
    __syncthreads();
    #pragma unroll
    for (int o = 1; o < 64; o <<= 1) {
        int u = (t >= o) ? sv[t - o] : 0;
        __syncthreads();
        sv[t] += u;
        __syncthreads();
    }
    if (t < nb) g_bpre[t] = sv[t] - v;
    if (t == nb - 1) g_off[n] = sv[t];
}
__global__ __launch_bounds__(256) void k_boff(int n) {
    __shared__ int sts[256];
    int b = blockIdx.x, t = threadIdx.x;
    int base = b * 1024 + t * 4;

    int c0 = 0, c1 = 0, c2 = 0, c3 = 0;
    if (base + 3 < n) {
        int4 v = *(const int4*)&g_cnt[base];
        c0 = v.x; c1 = v.y; c2 = v.z; c3 = v.w;
    } else {
        if (base + 0 < n) c0 = g_cnt[base + 0];
        if (base + 1 < n) c1 = g_cnt[base + 1];
        if (base + 2 < n) c2 = g_cnt[base + 2];
        if (base + 3 < n) c3 = g_cnt[base + 3];
    }
    int tsum = c0 + c1 + c2 + c3;
    sts[t] = tsum;
    __syncthreads();
    #pragma unroll
    for (int o = 1; o < 256; o <<= 1) {
        int u = (t >= o) ? sts[t - o] : 0;
        __syncthreads();
        sts[t] += u;
        __syncthreads();
    }
    int excl = g_bpre[b] + sts[t] - tsum;

    int o0 = excl, o1 = o0 + c0, o2 = o1 + c1, o3 = o2 + c2;
    if (base + 3 < n) {
        *(int4*)&g_off[base] = make_int4(o0, o1, o2, o3);
        *(int4*)&g_pos[base] = make_int4(o0, o1, o2, o3);
    } else {
        if (base + 0 < n) { g_off[base + 0] = o0; g_pos[base + 0] = o0; }
        if (base + 1 < n) { g_off[base + 1] = o1; g_pos[base + 1] = o1; }
        if (base + 2 < n) { g_off[base + 2] = o2; g_pos[base + 2] = o2; }
        if (base + 3 < n) { g_off[base + 3] = o3; g_pos[base + 3] = o3; }
    }
}
__global__ void k_fill(const int* __restrict__ src, const int* __restrict__ dst, int e) {
    int i = blockIdx.x * blockDim.x + threadIdx.x;
    if (i < e) {
        int d = dst[i];
        int p = atomicAdd(&g_pos[d], 1);
        g_csr[p] = src[i];
    }
}

// ---------------- fp16 tensor-core GEMM, cp.async double-buffered ------------
// CTA tile: 128 x BN (BN covers the full output width; grid.x == 1).
// 8 warps (2x4), warp tile 64 x (JN*8), JN = BN/32.
#define AW 40            // halves per As row (32 + 8 pad)

__device__ __forceinline__ void cpa16(unsigned dst, const void* src, int srcsize) {
    asm volatile("cp.async.ca.shared.global [%0], [%1], 16, %2;"
                 :: "r"(dst), "l"(src), "r"(srcsize));
}

template<int BN>
__global__ __launch_bounds__(256, 1) void sgemm_f16(
    int M, int K,
    const __half* __restrict__ A, const __half* __restrict__ B, __half* __restrict__ C)
{
    constexpr int JN   = BN / 32;        // b-fragments per warp
    constexpr int BW   = BN + 8;         // halves per Bs row
    constexpr int ABUF = 128 * AW * 2;   // bytes per A stage
    constexpr int BBUF = 32 * BW * 2;    // bytes per B stage
    constexpr int CPR  = BN / 8;         // B 16B-chunks per row
    constexpr int BIT  = 4 * BN / 256;   // B staging iterations (chunks/256)

    extern __shared__ __align__(16) char smem[];
    __half* As = (__half*)smem;
    __half* Bs = (__half*)(smem + 2 * ABUF);

    int tid  = threadIdx.x;
    int lane = tid & 31;
    int warp = tid >> 5;
    int warpm = warp >> 2;               // 0..1
    int warpn = warp & 3;                // 0..3

    int blockM = blockIdx.x * 128;

    unsigned asA = (unsigned)__cvta_generic_to_shared(As);
    unsigned asB = (unsigned)__cvta_generic_to_shared(Bs);

    int a_row = (lane & 7) + ((lane >> 3) & 1) * 8;
    int a_k8  = (lane >> 4) * 8;
    int b_row = lane & 15;

    float c[4][JN][4];
    #pragma unroll
    for (int i = 0; i < 4; i++)
        #pragma unroll
        for (int j = 0; j < JN; j++)
            #pragma unroll
            for (int q = 0; q < 4; q++) c[i][j][q] = 0.0f;

    int KT = K >> 5;

    auto load_stage = [&](int kt, int buf) {
        int k0 = kt << 5;
        #pragma unroll
        for (int li = 0; li < 2; li++) {
            int v = tid + li * 256;
            int arow = v >> 2;
            int acnk = v & 3;
            const __half* Ap = A + (size_t)(blockM + arow) * K + k0 + acnk * 8;
            cpa16(asA + buf * ABUF + (arow * AW + acnk * 8) * 2, Ap,
                  (blockM + arow < M) ? 16 : 0);
        }
        #pragma unroll
        for (int li = 0; li < BIT; li++) {
            int v = tid + li * 256;
            int brow = v / CPR;
            int bcnk = v % CPR;
            const __half* Bp = B + (size_t)(k0 + brow) * BN + bcnk * 8;
            cpa16(asB + buf * BBUF + (brow * BW + bcnk * 8) * 2, Bp, 16);
        }
        asm volatile("cp.async.commit_group;");
    };

    load_stage(0, 0);

    for (int kt = 0; kt < KT; kt++) {
        int buf = kt & 1;
        if (kt + 1 < KT) {
            load_stage(kt + 1, buf ^ 1);
            asm volatile("cp.async.wait_group 1;");
        } else {
            asm volatile("cp.async.wait_group 0;");
        }
        __syncthreads();

        unsigned aBase = asA + buf * ABUF;
        unsigned bBase = asB + buf * BBUF;

        #pragma unroll
        for (int kc = 0; kc < 32; kc += 16) {
            unsigned a[4][4];
            #pragma unroll
            for (int i = 0; i < 4; i++) {
                unsigned addr = aBase +
                    (((warpm * 64 + i * 16 + a_row) * AW) + kc + a_k8) * 2;
                asm volatile("ldmatrix.sync.aligned.m8n8.x4.shared.b16 "
                             "{%0,%1,%2,%3}, [%4];"
                             : "=r"(a[i][0]), "=r"(a[i][1]),
                               "=r"(a[i][2]), "=r"(a[i][3]) : "r"(addr));
            }
            #pragma unroll
            for (int j = 0; j < JN; j++) {
                unsigned b[2];
                unsigned addr = bBase +
                    (((kc + b_row) * BW) + warpn * JN * 8 + j * 8) * 2;
                asm volatile("ldmatrix.sync.aligned.m8n8.x2.trans.shared.b16 "
                             "{%0,%1}, [%2];"
                             : "=r"(b[0]), "=r"(b[1]) : "r"(addr));
                #pragma unroll
                for (int i = 0; i < 4; i++) {
                    asm volatile(
                        "mma.sync.aligned.m16n8k16.row.col.f32.f16.f16.f32 "
                        "{%0,%1,%2,%3},{%4,%5,%6,%7},{%8,%9},{%0,%1,%2,%3};"
                        : "+f"(c[i][j][0]), "+f"(c[i][j][1]),
                          "+f"(c[i][j][2]), "+f"(c[i][j][3])
                        : "r"(a[i][0]), "r"(a[i][1]), "r"(a[i][2]), "r"(a[i][3]),
                          "r"(b[0]), "r"(b[1]));
                }
            }
        }
        __syncthreads();
    }

    int r = lane >> 2, q = lane & 3;
    #pragma unroll
    for (int i = 0; i < 4; i++) {
        int gr0 = blockM + warpm * 64 + i * 16 + r;
        int gr1 = gr0 + 8;
        float dv0 = (gr0 < M) ? g_deg[gr0] : 0.f;
        float dv1 = (gr1 < M) ? g_deg[gr1] : 0.f;
        #pragma unroll
        for (int j = 0; j < JN; j++) {
            int gc = warpn * JN * 8 + j * 8 + 2 * q;
            if (gr0 < M)
                *(__half2*)(C + (size_t)gr0 * BN + gc) =
                    __floats2half2_rn(c[i][j][0] * dv0, c[i][j][1] * dv0);
            if (gr1 < M)
                *(__half2*)(C + (size_t)gr1 * BN + gc) =
                    __floats2half2_rn(c[i][j][2] * dv1, c[i][j][3] * dv1);
        }
    }
}

// ---------------- fused CSR aggregation (fp16 in/out) ------------------------
template<int F>
__global__ __launch_bounds__(F / 2) void k_agg(
    const __half* __restrict__ hp, const float* __restrict__ b,
    __half* __restrict__ out)
{
    const int T = F / 2;
    __shared__ int sids[T];
    int node = blockIdx.x;
    int t = threadIdx.x;

    int beg = g_off[node], end = g_off[node + 1];
    float accx = 0.f, accy = 0.f;

    for (int e0 = beg; e0 < end; e0 += T) {
        int ne = min(T, end - e0);
        __syncthreads();
        if (t < ne) sids[t] = g_csr[e0 + t];
        __syncthreads();
        #pragma unroll 4
        for (int j = 0; j < ne; j++) {
            float2 f = __half22float2(
                *(const __half2*)(hp + (size_t)sids[j] * F + 2 * t));
            accx += f.x; accy += f.y;
        }
    }

    float dv = g_deg[node];
    float2 sv = __half22float2(*(const __half2*)(hp + (size_t)node * F + 2 * t));
    float ox = fmaxf(dv * (accx + sv.x) + b[2 * t],     0.f);
    float oy = fmaxf(dv * (accy + sv.y) + b[2 * t + 1], 0.f);
    *(__half2*)(out + (size_t)node * F + 2 * t) = __floats2half2_rn(ox, oy);
}

// ---------------- classifier (HMMA) + log_softmax ----------------------------
__global__ __launch_bounds__(256) void k_cls(
    const __half* __restrict__ X, const __half* __restrict__ Wc,
    const float* __restrict__ bc, float* __restrict__ out, int n)
{
    __shared__ __align__(16) __half sX[128][136];
    __shared__ __align__(16) __half sW[128][72];

    int tid = threadIdx.x, lane = tid & 31, w = tid >> 5;
    int blockM = blockIdx.x * 128;

    #pragma unroll
    for (int it = 0; it < 8; it++) {
        int v = tid + it * 256;
        int row = v >> 4, ck = v & 15;
        int gr = blockM + row;
        uint4 val = make_uint4(0u, 0u, 0u, 0u);
        if (gr < n) val = *(const uint4*)(X + (size_t)gr * FMID + ck * 8);
        *(uint4*)&sX[row][ck * 8] = val;
    }
    #pragma unroll
    for (int it = 0; it < 4; it++) {
        int v = tid + it * 256;
        int row = v >> 3, ck = v & 7;
        *(uint4*)&sW[row][ck * 8] = *(const uint4*)(Wc + row * FOUT + ck * 8);
    }
    __syncthreads();

    int a_row = (lane & 7) + ((lane >> 3) & 1) * 8;
    int a_k8  = (lane >> 4) * 8;
    int b_row = lane & 15;

    float c[8][4];
    #pragma unroll
    for (int j = 0; j < 8; j++)
        #pragma unroll
        for (int q = 0; q < 4; q++) c[j][q] = 0.0f;

    #pragma unroll
    for (int k = 0; k < 8; k++) {
        unsigned a[4];
        unsigned addr = (unsigned)__cvta_generic_to_shared(
            &sX[w * 16 + a_row][k * 16 + a_k8]);
        asm volatile("ldmatrix.sync.aligned.m8n8.x4.shared.b16 {%0,%1,%2,%3}, [%4];"
                     : "=r"(a[0]), "=r"(a[1]), "=r"(a[2]), "=r"(a[3]) : "r"(addr));
        #pragma unroll
        for (int j = 0; j < 8; j++) {
            unsigned b[2];
            unsigned baddr = (unsigned)__cvta_generic_to_shared(
                &sW[k * 16 + b_row][j * 8]);
            asm volatile("ldmatrix.sync.aligned.m8n8.x2.trans.shared.b16 {%0,%1}, [%2];"
                         : "=r"(b[0]), "=r"(b[1]) : "r"(baddr));
            asm volatile(
                "mma.sync.aligned.m16n8k16.row.col.f32.f16.f16.f32 "
                "{%0,%1,%2,%3},{%4,%5,%6,%7},{%8,%9},{%0,%1,%2,%3};"
                : "+f"(c[j][0]), "+f"(c[j][1]), "+f"(c[j][2]), "+f"(c[j][3])
                : "r"(a[0]), "r"(a[1]), "r"(a[2]), "r"(a[3]),
                  "r"(b[0]), "r"(b[1]));
        }
    }

    int r = lane >> 2, q = lane & 3;

    #pragma unroll
    for (int j = 0; j < 8; j++) {
        float2 bb = *(const float2*)(bc + j * 8 + 2 * q);
        c[j][0] += bb.x; c[j][1] += bb.y;
        c[j][2] += bb.x; c[j][3] += bb.y;
    }

    float m0 = -1e30f, m1 = -1e30f;
    #pragma unroll
    for (int j = 0; j < 8; j++) {
        m0 = fmaxf(m0, fmaxf(c[j][0], c[j][1]));
        m1 = fmaxf(m1, fmaxf(c[j][2], c[j][3]));
    }
    m0 = fmaxf(m0, __shfl_xor_sync(0xffffffffu, m0, 1));
    m0 = fmaxf(m0, __shfl_xor_sync(0xffffffffu, m0, 2));
    m1 = fmaxf(m1, __shfl_xor_sync(0xffffffffu, m1, 1));
    m1 = fmaxf(m1, __shfl_xor_sync(0xffffffffu, m1, 2));

    float s0 = 0.f, s1 = 0.f;
    #pragma unroll
    for (int j = 0; j < 8; j++) {
        s0 += expf(c[j][0] - m0) + expf(c[j][1] - m0);
        s1 += expf(c[j][2] - m1) + expf(c[j][3] - m1);
    }
    s0 += __shfl_xor_sync(0xffffffffu, s0, 1);
    s0 += __shfl_xor_sync(0xffffffffu, s0, 2);
    s1 += __shfl_xor_sync(0xffffffffu, s1, 1);
    s1 += __shfl_xor_sync(0xffffffffu, s1, 2);

    float l0 = m0 + logf(s0);
    float l1 = m1 + logf(s1);

    int gr0 = blockM + w * 16 + r;
    int gr1 = gr0 + 8;
    #pragma unroll
    for (int j = 0; j < 8; j++) {
        int gc = j * 8 + 2 * q;
        if (gr0 < n)
            *(float2*)(out + (size_t)gr0 * FOUT + gc) =
                make_float2(c[j][0] - l0, c[j][1] - l0);
        if (gr1 < n)
            *(float2*)(out + (size_t)gr1 * FOUT + gc) =
                make_float2(c[j][2] - l1, c[j][3] - l1);
    }
}

// ---------------- launch ------------------------------------------------------
extern "C" void kernel_launch(void* const* d_in, const int* in_sizes, int n_in,
                              void* d_out, int out_size)
{
    const float* x   = (const float*)d_in[0];
    const int*   ei  = (const int*)  d_in[1];
    const float* W1  = (const float*)d_in[2];
    const float* b1  = (const float*)d_in[3];
    const float* W2  = (const float*)d_in[4];
    const float* b2  = (const float*)d_in[5];
    const float* Wc  = (const float*)d_in[6];
    const float* bc  = (const float*)d_in[7];
    float* out = (float*)d_out;

    int N = in_sizes[0] / FIN;
    int E = in_sizes[1] / 2;
    const int* src = ei;
    const int* dst = ei + E;

    __half *xh, *w1h, *w2h, *wch, *h1h, *x2h, *h2h, *x3h;
    cudaGetSymbolAddress((void**)&xh,  g_xh);
    cudaGetSymbolAddress((void**)&w1h, g_w1h);
    cudaGetSymbolAddress((void**)&w2h, g_w2h);
    cudaGetSymbolAddress((void**)&wch, g_wch);
    cudaGetSymbolAddress((void**)&h1h, g_h1h);
    cudaGetSymbolAddress((void**)&x2h, g_x2h);
    cudaGetSymbolAddress((void**)&h2h, g_h2h);
    cudaGetSymbolAddress((void**)&x3h, g_x3h);

    // dynamic smem sizes
    const int SM1 = 2 * (128 * AW * 2) + 2 * (32 * (FHID + 8) * 2);  // 54272
    const int SM2 = 2 * (128 * AW * 2) + 2 * (32 * (FMID + 8) * 2);  // 37888
    cudaFuncSetAttribute(sgemm_f16<FHID>,
                         cudaFuncAttributeMaxDynamicSharedMemorySize, SM1);
    cudaFuncSetAttribute(sgemm_f16<FMID>,
                         cudaFuncAttributeMaxDynamicSharedMemorySize, SM2);

    int nb = (N + 1023) / 1024;
    int nx = N * FIN;
    int tot = nx + FIN * FHID + FHID * FMID + FMID * FOUT;

    // 0: conversions + cnt zero
    k_tohalf_all<<<(tot / 8 + 255) / 256, 256>>>(x, W1, W2, Wc, nx);
    // 1-2: degree
    k_hist<<<(E + 255) / 256, 256>>>(dst, E);
    k_dinv<<<(N + 255) / 256, 256>>>(N);
    // 3: GEMM1 (ncu capture slot)
    sgemm_f16<FHID><<<(N + 127) / 128, 256, SM1>>>(N, FIN, xh, w1h, h1h);
    // 4-7: CSR build
    k_bsum<<<nb, 256>>>(N);
    k_bscan<<<1, 64>>>(nb, N);
    k_boff<<<nb, 256>>>(N);
    k_fill<<<(E + 255) / 256, 256>>>(src, dst, E);
    // 8: agg1
    k_agg<FHID><<<N, FHID / 2>>>(h1h, b1, x2h);
    // 9: GEMM2
    sgemm_f16<FMID><<<(N + 127) / 128, 256, SM2>>>(N, FHID, x2h, w2h, h2h);
    // 10: agg2
    k_agg<FMID><<<N, FMID / 2>>>(h2h, b2, x3h);
    // 11: classifier
    k_cls<<<(N + 127) / 128, 256>>>(x3h, wch, bc, out, N);
}

// round 17
// speedup vs baseline: 5.0956x; 1.1540x over previous
#include <cuda_runtime.h>
#include <cuda_fp16.h>
#include <math.h>

#define NN   50000
#define EE   800000
#define FIN  512
#define FHID 256
#define FMID 128
#define FOUT 64

// ---------------- scratch (static device globals) ----------------------------
__device__ __half g_xh [(size_t)NN * FIN];
__device__ __half g_w1h[FIN * FHID];
__device__ __half g_w2h[FHID * FMID];
__device__ __half g_wch[FMID * FOUT];
__device__ __half g_h1h[(size_t)NN * FHID];
__device__ __half g_x2h[(size_t)NN * FHID];
__device__ __half g_h2h[(size_t)NN * FMID];
__device__ __half g_x3h[(size_t)NN * FMID];
__device__ float  g_deg[NN];
__device__ int    g_cnt[NN + 4];
__device__ int    g_off[NN + 1];
__device__ int    g_pos[NN];
__device__ int    g_csr[EE];
__device__ int    g_bsum[256];
__device__ int    g_bpre[256];

// ---------------- fused fp32->fp16 conversion (+ cnt zeroing) ----------------
__global__ void k_tohalf_all(const float* __restrict__ x,
                             const float* __restrict__ W1,
                             const float* __restrict__ W2,
                             const float* __restrict__ Wc,
                             int nx)
{
    int gid = blockIdx.x * blockDim.x + threadIdx.x;
    {
        int z = gid * 8;
        if (z < NN + 4) {
            #pragma unroll
            for (int j = 0; j < 8; j++)
                if (z + j < NN + 4) g_cnt[z + j] = 0;
        }
    }
    const int n1 = FIN * FHID, n2 = FHID * FMID, n3 = FMID * FOUT;
    int i = gid * 8;
    const float* s; __half* d; int j;
    if (i < nx)                     { s = x;  d = g_xh;  j = i; }
    else if (i < nx + n1)           { s = W1; d = g_w1h; j = i - nx; }
    else if (i < nx + n1 + n2)      { s = W2; d = g_w2h; j = i - nx - n1; }
    else if (i < nx + n1 + n2 + n3) { s = Wc; d = g_wch; j = i - nx - n1 - n2; }
    else return;
    float4 v0 = *(const float4*)(s + j);
    float4 v1 = *(const float4*)(s + j + 4);
    *(__half2*)(d + j)     = __floats2half2_rn(v0.x, v0.y);
    *(__half2*)(d + j + 2) = __floats2half2_rn(v0.z, v0.w);
    *(__half2*)(d + j + 4) = __floats2half2_rn(v1.x, v1.y);
    *(__half2*)(d + j + 6) = __floats2half2_rn(v1.z, v1.w);
}

// ---------------- degree / CSR build -----------------------------------------
__global__ void k_hist(const int* __restrict__ dst, int e) {
    int i = blockIdx.x * blockDim.x + threadIdx.x;
    if (i < e) atomicAdd(&g_cnt[dst[i]], 1);
}
__global__ void k_dinv(int n) {
    int i = blockIdx.x * blockDim.x + threadIdx.x;
    if (i < n) g_deg[i] = rsqrtf(1.0f + (float)g_cnt[i]);
}
__global__ __launch_bounds__(256) void k_bsum(int n) {
    __shared__ int sw[8];
    int b = blockIdx.x, t = threadIdx.x;
    int base = b * 1024;
    int s = 0;
    #pragma unroll
    for (int j = 0; j < 4; j++) {
        int i = base + t + j * 256;
        if (i < n) s += g_cnt[i];
    }
    #pragma unroll
    for (int o = 16; o; o >>= 1) s += __shfl_xor_sync(0xffffffffu, s, o);
    if ((t & 31) == 0) sw[t >> 5] = s;
    __syncthreads();
    if (t == 0) {
        int tot = 0;
        #pragma unroll
        for (int w = 0; w < 8; w++) tot += sw[w];
        g_bsum[b] = tot;
    }
}
__global__ __launch_bounds__(64) void k_bscan(int nb, int n) {
    __shared__ int sv[64];
    int t = threadIdx.x;
    int v = (t < nb) ? g_bsum[t] : 0;
    sv[t] = v;
    __syncthreads();
    #pragma unroll
    for (int o = 1; o < 64; o <<= 1) {
        int u = (t >= o) ? sv[t - o] : 0;
        __syncthreads();
        sv[t] += u;
        __syncthreads();
    }
    if (t < nb) g_bpre[t] = sv[t] - v;
    if (t == nb - 1) g_off[n] = sv[t];
}
__global__ __launch_bounds__(256) void k_boff(int n) {
    __shared__ int sts[256];
    int b = blockIdx.x, t = threadIdx.x;
    int base = b * 1024 + t * 4;

    int c0 = 0, c1 = 0, c2 = 0, c3 = 0;
    if (base + 3 < n) {
        int4 v = *(const int4*)&g_cnt[base];
        c0 = v.x; c1 = v.y; c2 = v.z; c3 = v.w;
    } else {
        if (base + 0 < n) c0 = g_cnt[base + 0];
        if (base + 1 < n) c1 = g_cnt[base + 1];
        if (base + 2 < n) c2 = g_cnt[base + 2];
        if (base + 3 < n) c3 = g_cnt[base + 3];
    }
    int tsum = c0 + c1 + c2 + c3;
    sts[t] = tsum;
    __syncthreads();
    #pragma unroll
    for (int o = 1; o < 256; o <<= 1) {
        int u = (t >= o) ? sts[t - o] : 0;
        __syncthreads();
        sts[t] += u;
        __syncthreads();
    }
    int excl = g_bpre[b] + sts[t] - tsum;

    int o0 = excl, o1 = o0 + c0, o2 = o1 + c1, o3 = o2 + c2;
    if (base + 3 < n) {
        *(int4*)&g_off[base] = make_int4(o0, o1, o2, o3);
        *(int4*)&g_pos[base] = make_int4(o0, o1, o2, o3);
    } else {
        if (base + 0 < n) { g_off[base + 0] = o0; g_pos[base + 0] = o0; }
        if (base + 1 < n) { g_off[base + 1] = o1; g_pos[base + 1] = o1; }
        if (base + 2 < n) { g_off[base + 2] = o2; g_pos[base + 2] = o2; }
        if (base + 3 < n) { g_off[base + 3] = o3; g_pos[base + 3] = o3; }
    }
}
__global__ void k_fill(const int* __restrict__ src, const int* __restrict__ dst, int e) {
    int i = blockIdx.x * blockDim.x + threadIdx.x;
    if (i < e) {
        int d = dst[i];
        int p = atomicAdd(&g_pos[d], 1);
        g_csr[p] = src[i];
    }
}

// ---------------- fp16 tensor-core GEMM, 3-stage cp.async, 2 CTAs/SM ---------
// BM=128, BN=128, BK=32; 8 warps (2x4), warp tile 64x32.
#define AW 40                 // halves per As row (32 + 8 pad)
#define BW 136                // halves per Bs row (128 + 8 pad)
#define ABUF (128 * AW * 2)   // 10240 B per A stage
#define BBUF (32 * BW * 2)    // 8704 B per B stage
#define NSTG 3

__device__ __forceinline__ void cpa16(unsigned dst, const void* src, int srcsize) {
    asm volatile("cp.async.ca.shared.global [%0], [%1], 16, %2;"
                 :: "r"(dst), "l"(src), "r"(srcsize));
}

__global__ __launch_bounds__(256, 2) void sgemm_f16(
    int M, int N, int K,
    const __half* __restrict__ A, const __half* __restrict__ B, __half* __restrict__ C)
{
    extern __shared__ __align__(16) char smem[];
    unsigned asA = (unsigned)__cvta_generic_to_shared(smem);
    unsigned asB = asA + NSTG * ABUF;

    int tid  = threadIdx.x;
    int lane = tid & 31;
    int warp = tid >> 5;
    int warpm = warp >> 2;
    int warpn = warp & 3;

    int blockM = blockIdx.y * 128;
    int blockN = blockIdx.x * 128;

    int a_row = (lane & 7) + ((lane >> 3) & 1) * 8;
    int a_k8  = (lane >> 4) * 8;
    int b_row = lane & 15;

    float c[4][4][4];
    #pragma unroll
    for (int i = 0; i < 4; i++)
        #pragma unroll
        for (int j = 0; j < 4; j++)
            #pragma unroll
            for (int q = 0; q < 4; q++) c[i][j][q] = 0.0f;

    int KT = K >> 5;

    auto load_stage = [&](int kt, int buf) {
        int k0 = kt << 5;
        #pragma unroll
        for (int li = 0; li < 2; li++) {
            int v = tid + li * 256;
            int arow = v >> 2;
            int acnk = v & 3;
            const __half* Ap = A + (size_t)(blockM + arow) * K + k0 + acnk * 8;
            cpa16(asA + buf * ABUF + (arow * AW + acnk * 8) * 2, Ap,
                  (blockM + arow < M) ? 16 : 0);
        }
        #pragma unroll
        for (int li = 0; li < 2; li++) {
            int v = tid + li * 256;
            int brow = v >> 4;
            int bcnk = v & 15;
            const __half* Bp = B + (size_t)(k0 + brow) * N + blockN + bcnk * 8;
            cpa16(asB + buf * BBUF + (brow * BW + bcnk * 8) * 2, Bp, 16);
        }
        asm volatile("cp.async.commit_group;");
    };

    load_stage(0, 0);
    if (KT > 1) load_stage(1, 1);

    int buf = 0;
    for (int kt = 0; kt < KT; kt++) {
        if (kt + 1 < KT) asm volatile("cp.async.wait_group 1;");
        else             asm volatile("cp.async.wait_group 0;");
        __syncthreads();

        // prefetch stage kt+2 while computing kt
        if (kt + 2 < KT) {
            int nb = buf + 2; if (nb >= NSTG) nb -= NSTG;
            load_stage(kt + 2, nb);
        }

        unsigned aBase = asA + buf * ABUF;
        unsigned bBase = asB + buf * BBUF;

        #pragma unroll
        for (int kc = 0; kc < 32; kc += 16) {
            unsigned a[4][4], b[4][2];
            #pragma unroll
            for (int i = 0; i < 4; i++) {
                unsigned addr = aBase +
                    (((warpm * 64 + i * 16 + a_row) * AW) + kc + a_k8) * 2;
                asm volatile("ldmatrix.sync.aligned.m8n8.x4.shared.b16 "
                             "{%0,%1,%2,%3}, [%4];"
                             : "=r"(a[i][0]), "=r"(a[i][1]),
                               "=r"(a[i][2]), "=r"(a[i][3]) : "r"(addr));
            }
            #pragma unroll
            for (int j = 0; j < 4; j++) {
                unsigned addr = bBase +
                    (((kc + b_row) * BW) + warpn * 32 + j * 8) * 2;
                asm volatile("ldmatrix.sync.aligned.m8n8.x2.trans.shared.b16 "
                             "{%0,%1}, [%2];"
                             : "=r"(b[j][0]), "=r"(b[j][1]) : "r"(addr));
            }
            #pragma unroll
            for (int i = 0; i < 4; i++)
                #pragma unroll
                for (int j = 0; j < 4; j++) {
                    asm volatile(
                        "mma.sync.aligned.m16n8k16.row.col.f32.f16.f16.f32 "
                        "{%0,%1,%2,%3},{%4,%5,%6,%7},{%8,%9},{%0,%1,%2,%3};"
                        : "+f"(c[i][j][0]), "+f"(c[i][j][1]),
                          "+f"(c[i][j][2]), "+f"(c[i][j][3])
                        : "r"(a[i][0]), "r"(a[i][1]), "r"(a[i][2]), "r"(a[i][3]),
                          "r"(b[j][0]), "r"(b[j][1]));
                }
        }
        __syncthreads();
        if (++buf >= NSTG) buf = 0;
    }

    int r = lane >> 2, q = lane & 3;
    #pragma unroll
    for (int i = 0; i < 4; i++) {
        int gr0 = blockM + warpm * 64 + i * 16 + r;
        int gr1 = gr0 + 8;
        float dv0 = (gr0 < M) ? g_deg[gr0] : 0.f;
        float dv1 = (gr1 < M) ? g_deg[gr1] : 0.f;
        #pragma unroll
        for (int j = 0; j < 4; j++) {
            int gc = blockN + warpn * 32 + j * 8 + 2 * q;
            if (gr0 < M)
                *(__half2*)(C + (size_t)gr0 * N + gc) =
                    __floats2half2_rn(c[i][j][0] * dv0, c[i][j][1] * dv0);
            if (gr1 < M)
                *(__half2*)(C + (size_t)gr1 * N + gc) =
                    __floats2half2_rn(c[i][j][2] * dv1, c[i][j][3] * dv1);
        }
    }
}

// ---------------- warp-per-node CSR aggregation (fp16 in/out) ----------------
// out[d] = half( relu( dinv[d]*(h'[d] + sum h'[s]) + b ) )
// 32 lanes cover a row: F=256 -> 16B/lane (uint4), F=128 -> 8B/lane (uint2).
template<int F>
__global__ __launch_bounds__(128) void k_agg(
    const __half* __restrict__ hp, const float* __restrict__ b,
    __half* __restrict__ out, int nnodes)
{
    constexpr int HPL = F / 32;            // halves per lane (8 or 4)
    int node = blockIdx.x * 4 + (threadIdx.x >> 5);
    if (node >= nnodes) return;
    int lane = threadIdx.x & 31;

    float acc[HPL];
    #pragma unroll
    for (int p = 0; p < HPL; p++) acc[p] = 0.0f;

    int beg = g_off[node], end = g_off[node + 1];
    for (int e0 = beg; e0 < end; e0 += 32) {
        int ne = min(32, end - e0);
        int myid = (lane < ne) ? g_csr[e0 + lane] : 0;
        for (int j = 0; j < ne; j++) {
            int s = __shfl_sync(0xffffffffu, myid, j);
            const __half* row = hp + (size_t)s * F + lane * HPL;
            if (HPL == 8) {
                uint4 v = *(const uint4*)row;
                const __half2* h2 = (const __half2*)&v;
                #pragma unroll
                for (int p = 0; p < 4; p++) {
                    float2 f = __half22float2(h2[p]);
                    acc[2 * p] += f.x; acc[2 * p + 1] += f.y;
                }
            } else {
                uint2 v = *(const uint2*)row;
                const __half2* h2 = (const __half2*)&v;
                #pragma unroll
                for (int p = 0; p < 2; p++) {
                    float2 f = __half22float2(h2[p]);
                    acc[2 * p] += f.x; acc[2 * p + 1] += f.y;
                }
            }
        }
    }

    float dv = g_deg[node];
    const __half* self = hp + (size_t)node * F + lane * HPL;
    const float*  bp   = b + lane * HPL;
    __half2 res[HPL / 2];
    if (HPL == 8) {
        uint4 v = *(const uint4*)self;
        const __half2* h2 = (const __half2*)&v;
        #pragma unroll
        for (int p = 0; p < 4; p++) {
            float2 f = __half22float2(h2[p]);
            float ox = fmaxf(dv * (acc[2 * p]     + f.x) + bp[2 * p],     0.f);
            float oy = fmaxf(dv * (acc[2 * p + 1] + f.y) + bp[2 * p + 1], 0.f);
            res[p] = __floats2half2_rn(ox, oy);
        }
        *(uint4*)(out + (size_t)node * F + lane * HPL) = *(uint4*)res;
    } else {
        uint2 v = *(const uint2*)self;
        const __half2* h2 = (const __half2*)&v;
        #pragma unroll
        for (int p = 0; p < 2; p++) {
            float2 f = __half22float2(h2[p]);
            float ox = fmaxf(dv * (acc[2 * p]     + f.x) + bp[2 * p],     0.f);
            float oy = fmaxf(dv * (acc[2 * p + 1] + f.y) + bp[2 * p + 1], 0.f);
            res[p] = __floats2half2_rn(ox, oy);
        }
        *(uint2*)(out + (size_t)node * F + lane * HPL) = *(uint2*)res;
    }
}

// ---------------- classifier (HMMA) + log_softmax ----------------------------
__global__ __launch_bounds__(256) void k_cls(
    const __half* __restrict__ X, const __half* __restrict__ Wc,
    const float* __restrict__ bc, float* __restrict__ out, int n)
{
    __shared__ __align__(16) __half sX[128][136];
    __shared__ __align__(16) __half sW[128][72];

    int tid = threadIdx.x, lane = tid & 31, w = tid >> 5;
    int blockM = blockIdx.x * 128;

    #pragma unroll
    for (int it = 0; it < 8; it++) {
        int v = tid + it * 256;
        int row = v >> 4, ck = v & 15;
        int gr = blockM + row;
        uint4 val = make_uint4(0u, 0u, 0u, 0u);
        if (gr < n) val = *(const uint4*)(X + (size_t)gr * FMID + ck * 8);
        *(uint4*)&sX[row][ck * 8] = val;
    }
    #pragma unroll
    for (int it = 0; it < 4; it++) {
        int v = tid + it * 256;
        int row = v >> 3, ck = v & 7;
        *(uint4*)&sW[row][ck * 8] = *(const uint4*)(Wc + row * FOUT + ck * 8);
    }
    __syncthreads();

    int a_row = (lane & 7) + ((lane >> 3) & 1) * 8;
    int a_k8  = (lane >> 4) * 8;
    int b_row = lane & 15;

    float c[8][4];
    #pragma unroll
    for (int j = 0; j < 8; j++)
        #pragma unroll
        for (int q = 0; q < 4; q++) c[j][q] = 0.0f;

    #pragma unroll
    for (int k = 0; k < 8; k++) {
        unsigned a[4];
        unsigned addr = (unsigned)__cvta_generic_to_shared(
            &sX[w * 16 + a_row][k * 16 + a_k8]);
        asm volatile("ldmatrix.sync.aligned.m8n8.x4.shared.b16 {%0,%1,%2,%3}, [%4];"
                     : "=r"(a[0]), "=r"(a[1]), "=r"(a[2]), "=r"(a[3]) : "r"(addr));
        #pragma unroll
        for (int j = 0; j < 8; j++) {
            unsigned b[2];
            unsigned baddr = (unsigned)__cvta_generic_to_shared(
                &sW[k * 16 + b_row][j * 8]);
            asm volatile("ldmatrix.sync.aligned.m8n8.x2.trans.shared.b16 {%0,%1}, [%2];"
                         : "=r"(b[0]), "=r"(b[1]) : "r"(baddr));
            asm volatile(
                "mma.sync.aligned.m16n8k16.row.col.f32.f16.f16.f32 "
                "{%0,%1,%2,%3},{%4,%5,%6,%7},{%8,%9},{%0,%1,%2,%3};"
                : "+f"(c[j][0]), "+f"(c[j][1]), "+f"(c[j][2]), "+f"(c[j][3])
                : "r"(a[0]), "r"(a[1]), "r"(a[2]), "r"(a[3]),
                  "r"(b[0]), "r"(b[1]));
        }
    }

    int r = lane >> 2, q = lane & 3;

    #pragma unroll
    for (int j = 0; j < 8; j++) {
        float2 bb = *(const float2*)(bc + j * 8 + 2 * q);
        c[j][0] += bb.x; c[j][1] += bb.y;
        c[j][2] += bb.x; c[j][3] += bb.y;
    }

    float m0 = -1e30f, m1 = -1e30f;
    #pragma unroll
    for (int j = 0; j < 8; j++) {
        m0 = fmaxf(m0, fmaxf(c[j][0], c[j][1]));
        m1 = fmaxf(m1, fmaxf(c[j][2], c[j][3]));
    }
    m0 = fmaxf(m0, __shfl_xor_sync(0xffffffffu, m0, 1));
    m0 = fmaxf(m0, __shfl_xor_sync(0xffffffffu, m0, 2));
    m1 = fmaxf(m1, __shfl_xor_sync(0xffffffffu, m1, 1));
    m1 = fmaxf(m1, __shfl_xor_sync(0xffffffffu, m1, 2));

    float s0 = 0.f, s1 = 0.f;
    #pragma unroll
    for (int j = 0; j < 8; j++) {
        s0 += expf(c[j][0] - m0) + expf(c[j][1] - m0);
        s1 += expf(c[j][2] - m1) + expf(c[j][3] - m1);
    }
    s0 += __shfl_xor_sync(0xffffffffu, s0, 1);
    s0 += __shfl_xor_sync(0xffffffffu, s0, 2);
    s1 += __shfl_xor_sync(0xffffffffu, s1, 1);
    s1 += __shfl_xor_sync(0xffffffffu, s1, 2);

    float l0 = m0 + logf(s0);
    float l1 = m1 + logf(s1);

    int gr0 = blockM + w * 16 + r;
    int gr1 = gr0 + 8;
    #pragma unroll
    for (int j = 0; j < 8; j++) {
        int gc = j * 8 + 2 * q;
        if (gr0 < n)
            *(float2*)(out + (size_t)gr0 * FOUT + gc) =
                make_float2(c[j][0] - l0, c[j][1] - l0);
        if (gr1 < n)
            *(float2*)(out + (size_t)gr1 * FOUT + gc) =
                make_float2(c[j][2] - l1, c[j][3] - l1);
    }
}

// ---------------- launch ------------------------------------------------------
extern "C" void kernel_launch(void* const* d_in, const int* in_sizes, int n_in,
                              void* d_out, int out_size)
{
    const float* x   = (const float*)d_in[0];
    const int*   ei  = (const int*)  d_in[1];
    const float* W1  = (const float*)d_in[2];
    const float* b1  = (const float*)d_in[3];
    const float* W2  = (const float*)d_in[4];
    const float* b2  = (const float*)d_in[5];
    const float* Wc  = (const float*)d_in[6];
    const float* bc  = (const float*)d_in[7];
    float* out = (float*)d_out;

    int N = in_sizes[0] / FIN;
    int E = in_sizes[1] / 2;
    const int* src = ei;
    const int* dst = ei + E;

    __half *xh, *w1h, *w2h, *wch, *h1h, *x2h, *h2h, *x3h;
    cudaGetSymbolAddress((void**)&xh,  g_xh);
    cudaGetSymbolAddress((void**)&w1h, g_w1h);
    cudaGetSymbolAddress((void**)&w2h, g_w2h);
    cudaGetSymbolAddress((void**)&wch, g_wch);
    cudaGetSymbolAddress((void**)&h1h, g_h1h);
    cudaGetSymbolAddress((void**)&x2h, g_x2h);
    cudaGetSymbolAddress((void**)&h2h, g_h2h);
    cudaGetSymbolAddress((void**)&x3h, g_x3h);

    const int SMB = NSTG * (ABUF + BBUF);    // 56832 bytes
    cudaFuncSetAttribute(sgemm_f16,
                         cudaFuncAttributeMaxDynamicSharedMemorySize, SMB);

    int nb = (N + 1023) / 1024;
    int nx = N * FIN;
    int tot = nx + FIN * FHID + FHID * FMID + FMID * FOUT;

    // 0: conversions + cnt zero
    k_tohalf_all<<<(tot / 8 + 255) / 256, 256>>>(x, W1, W2, Wc, nx);
    // 1-2: degree
    k_hist<<<(E + 255) / 256, 256>>>(dst, E);
    k_dinv<<<(N + 255) / 256, 256>>>(N);
    // 3: GEMM1 (ncu capture slot)
    {
        dim3 grid(FHID / 128, (N + 127) / 128);
        sgemm_f16<<<grid, 256, SMB>>>(N, FHID, FIN, xh, w1h, h1h);
    }
    // 4-7: CSR build
    k_bsum<<<nb, 256>>>(N);
    k_bscan<<<1, 64>>>(nb, N);
    k_boff<<<nb, 256>>>(N);
    k_fill<<<(E + 255) / 256, 256>>>(src, dst, E);
    // 8: agg1
    k_agg<FHID><<<(N + 3) / 4, 128>>>(h1h, b1, x2h, N);
    // 9: GEMM2
    {
        dim3 grid(FMID / 128, (N + 127) / 128);
        sgemm_f16<<<grid, 256, SMB>>>(N, FMID, FHID, x2h, w2h, h2h);
    }
    // 10: agg2
    k_agg<FMID><<<(N + 3) / 4, 128>>>(h2h, b2, x3h, N);
    // 11: classifier
    k_cls<<<(N + 127) / 128, 256>>>(x3h, wch, bc, out, N);
}